// round 1
// baseline (speedup 1.0000x reference)
#include <cuda_runtime.h>

#define NSEQ 512
#define CDIM 128
#define NN (NSEQ*NSEQ)   // 262144 rows

// scratch in d-major layout: buf[d][p][q] = value at z-position (p,q), channel d
__device__ float g_bufA[(size_t)CDIM*NN];   // a[i,k,d]    -> [d][i][k]
__device__ float g_bufB[(size_t)CDIM*NN];   // b[k,j,d]    -> [d][k][j]
__device__ float g_bufG[(size_t)CDIM*NN];   // gate[i,j,d] -> [d][i][j]
__device__ float g_bufX[(size_t)CDIM*NN];   // x[i,j,d]    -> [d][i][j]

__device__ __forceinline__ float sigmoidf_(float x) { return 1.f/(1.f + __expf(-x)); }

// cooperative load of a 128x128 weight matrix W[o][c] into smem with stride 129
__device__ __forceinline__ void loadW(float* dst, const float* __restrict__ W, int tid) {
    for (int idx = tid; idx < CDIM*CDIM; idx += 256) {
        int o = idx >> 7, c = idx & 127;
        dst[o*129 + c] = W[idx];
    }
}

// P1 = zn @ W1^T + b1, P2 = zn @ W2^T + b2 over a 64x128 zn tile.
// thread (tr,tc): rows 4*tr..4*tr+3, cols tc+16*oo (oo=0..7)
__device__ __forceinline__ void gemm_pair(
    const float* s_z, const float* s_w1, const float* s_w2,
    const float* __restrict__ b1, const float* __restrict__ b2,
    int tr, int tc, float a1[4][8], float a2[4][8])
{
    float bb1[8], bb2[8];
    #pragma unroll
    for (int oo = 0; oo < 8; ++oo) { int o = tc + 16*oo; bb1[oo] = b1[o]; bb2[oo] = b2[o]; }
    #pragma unroll
    for (int rr = 0; rr < 4; ++rr)
        #pragma unroll
        for (int oo = 0; oo < 8; ++oo) { a1[rr][oo] = bb1[oo]; a2[rr][oo] = bb2[oo]; }

    #pragma unroll 4
    for (int c = 0; c < CDIM; ++c) {
        float zr[4];
        #pragma unroll
        for (int rr = 0; rr < 4; ++rr) zr[rr] = s_z[(4*tr+rr)*129 + c];
        #pragma unroll
        for (int oo = 0; oo < 8; ++oo) {
            float w1 = s_w1[(tc+16*oo)*129 + c];
            float w2 = s_w2[(tc+16*oo)*129 + c];
            #pragma unroll
            for (int rr = 0; rr < 4; ++rr) {
                a1[rr][oo] = fmaf(zr[rr], w1, a1[rr][oo]);
                a2[rr][oo] = fmaf(zr[rr], w2, a2[rr][oo]);
            }
        }
    }
}

__device__ __forceinline__ void gemm_single(
    const float* s_z, const float* s_w1, const float* __restrict__ b1,
    int tr, int tc, float a1[4][8])
{
    float bb1[8];
    #pragma unroll
    for (int oo = 0; oo < 8; ++oo) bb1[oo] = b1[tc + 16*oo];
    #pragma unroll
    for (int rr = 0; rr < 4; ++rr)
        #pragma unroll
        for (int oo = 0; oo < 8; ++oo) a1[rr][oo] = bb1[oo];

    #pragma unroll 4
    for (int c = 0; c < CDIM; ++c) {
        float zr[4];
        #pragma unroll
        for (int rr = 0; rr < 4; ++rr) zr[rr] = s_z[(4*tr+rr)*129 + c];
        #pragma unroll
        for (int oo = 0; oo < 8; ++oo) {
            float w1 = s_w1[(tc+16*oo)*129 + c];
            #pragma unroll
            for (int rr = 0; rr < 4; ++rr) a1[rr][oo] = fmaf(zr[rr], w1, a1[rr][oo]);
        }
    }
}

// stage result [64 rows x 128 d] through smem transpose, flush coalesced to gdst[d][row]
__device__ __forceinline__ void write_transposed(
    const float vals[4][8], float* __restrict__ gdst, float* s_os,
    int tid, int tr, int tc, int r0)
{
    __syncthreads();   // everyone done reading the region s_os aliases
    #pragma unroll
    for (int rr = 0; rr < 4; ++rr)
        #pragma unroll
        for (int oo = 0; oo < 8; ++oo)
            s_os[(tc+16*oo)*65 + 4*tr + rr] = vals[rr][oo];
    __syncthreads();
    for (int idx = tid; idx < CDIM*64; idx += 256) {
        int o = idx >> 6, rw = idx & 63;
        gdst[(size_t)o*NN + r0 + rw] = s_os[o*65 + rw];
    }
}

// ---------------------------------------------------------------------------
// Stage 1: LN(z) + gated projections a, b + gate, written d-major
// ---------------------------------------------------------------------------
__global__ void __launch_bounds__(256) stage1_kernel(
    const float* __restrict__ z,   const float* __restrict__ mask,
    const float* __restrict__ lnw, const float* __restrict__ lnb,
    const float* __restrict__ agw, const float* __restrict__ agb,
    const float* __restrict__ apw, const float* __restrict__ apb,
    const float* __restrict__ bgw, const float* __restrict__ bgb,
    const float* __restrict__ bpw, const float* __restrict__ bpb,
    const float* __restrict__ gw,  const float* __restrict__ gwb)
{
    extern __shared__ float sm[];
    float* s_z  = sm;                    // 64*129
    float* s_w1 = sm + 64*129;           // 128*129
    float* s_w2 = s_w1 + 128*129;        // 128*129  (also output staging, 128*65)
    float* s_m  = s_w2 + 128*129;        // 64

    const int tid = threadIdx.x;
    const int r0  = blockIdx.x * 64;     // global row (= i*512 + k)

    // load z tile, coalesced
    for (int idx = tid; idx < 64*CDIM; idx += 256) {
        int rw = idx >> 7, c = idx & 127;
        s_z[rw*129 + c] = z[(size_t)(r0 + rw)*CDIM + c];
    }
    if (tid < 64) s_m[tid] = mask[r0 + tid];
    __syncthreads();

    // layernorm, 4 threads per row
    {
        int rw = tid >> 2, l = tid & 3;
        float s = 0.f;
        for (int c = l; c < CDIM; c += 4) s += s_z[rw*129 + c];
        s += __shfl_down_sync(0xffffffffu, s, 1, 4);
        s += __shfl_down_sync(0xffffffffu, s, 2, 4);
        float mu = __shfl_sync(0xffffffffu, s, 0, 4) * (1.f/CDIM);
        float v = 0.f;
        for (int c = l; c < CDIM; c += 4) { float dlt = s_z[rw*129 + c] - mu; v = fmaf(dlt, dlt, v); }
        v += __shfl_down_sync(0xffffffffu, v, 1, 4);
        v += __shfl_down_sync(0xffffffffu, v, 2, 4);
        float rs = rsqrtf(__shfl_sync(0xffffffffu, v, 0, 4) * (1.f/CDIM) + 1e-5f);
        for (int c = l; c < CDIM; c += 4)
            s_z[rw*129 + c] = (s_z[rw*129 + c] - mu) * rs * lnw[c] + lnb[c];
    }
    __syncthreads();

    const int tr = tid >> 4, tc = tid & 15;
    float a1[4][8], a2[4][8];

    // ---- a = mask * sigmoid(zn@agw^T+agb) * (zn@apw^T+apb) ----
    loadW(s_w1, agw, tid); loadW(s_w2, apw, tid);
    __syncthreads();
    gemm_pair(s_z, s_w1, s_w2, agb, apb, tr, tc, a1, a2);
    #pragma unroll
    for (int rr = 0; rr < 4; ++rr) {
        float m = s_m[4*tr + rr];
        #pragma unroll
        for (int oo = 0; oo < 8; ++oo) a1[rr][oo] = m * sigmoidf_(a1[rr][oo]) * a2[rr][oo];
    }
    write_transposed(a1, g_bufA, s_w2, tid, tr, tc, r0);
    __syncthreads();

    // ---- b ----
    loadW(s_w1, bgw, tid); loadW(s_w2, bpw, tid);
    __syncthreads();
    gemm_pair(s_z, s_w1, s_w2, bgb, bpb, tr, tc, a1, a2);
    #pragma unroll
    for (int rr = 0; rr < 4; ++rr) {
        float m = s_m[4*tr + rr];
        #pragma unroll
        for (int oo = 0; oo < 8; ++oo) a1[rr][oo] = m * sigmoidf_(a1[rr][oo]) * a2[rr][oo];
    }
    write_transposed(a1, g_bufB, s_w2, tid, tr, tc, r0);
    __syncthreads();

    // ---- gate = sigmoid(zn@gw^T + gwb) ----
    loadW(s_w1, gw, tid);
    __syncthreads();
    gemm_single(s_z, s_w1, gwb, tr, tc, a1);
    #pragma unroll
    for (int rr = 0; rr < 4; ++rr)
        #pragma unroll
        for (int oo = 0; oo < 8; ++oo) a1[rr][oo] = sigmoidf_(a1[rr][oo]);
    write_transposed(a1, g_bufG, s_w2, tid, tr, tc, r0);
}

// ---------------------------------------------------------------------------
// Stage 2: per-d SGEMM, x[d] = a[d] (512x512) @ b[d] (512x512)
// 128x128 block tile, 8x8 microtile, K-tile 16
// ---------------------------------------------------------------------------
__global__ void __launch_bounds__(256) stage2_kernel()
{
    const int d  = blockIdx.z;
    const float* __restrict__ A = g_bufA + (size_t)d*NN;
    const float* __restrict__ B = g_bufB + (size_t)d*NN;
    float* __restrict__ C = g_bufX + (size_t)d*NN;
    const int i0 = blockIdx.y * 128, j0 = blockIdx.x * 128;

    __shared__ float As[16][132];   // As[c][i] (transposed)
    __shared__ float Bs[16][128];   // Bs[c][j]

    float acc[8][8];
    #pragma unroll
    for (int a = 0; a < 8; ++a)
        #pragma unroll
        for (int b = 0; b < 8; ++b) acc[a][b] = 0.f;

    const int tid = threadIdx.x;
    const int ty = tid >> 4, tx = tid & 15;

    for (int kt = 0; kt < NSEQ; kt += 16) {
        #pragma unroll
        for (int it = 0; it < 2; ++it) {
            int idx = it*256 + tid;           // 0..511
            int r  = idx >> 2, cq = idx & 3;
            float4 v = *(const float4*)(A + (size_t)(i0 + r)*NSEQ + kt + cq*4);
            As[cq*4+0][r] = v.x; As[cq*4+1][r] = v.y;
            As[cq*4+2][r] = v.z; As[cq*4+3][r] = v.w;
            int rb = idx >> 5, cb = idx & 31;
            *(float4*)&Bs[rb][cb*4] = *(const float4*)(B + (size_t)(kt + rb)*NSEQ + j0 + cb*4);
        }
        __syncthreads();
        #pragma unroll
        for (int c = 0; c < 16; ++c) {
            float4 av0 = *(const float4*)&As[c][8*ty];
            float4 av1 = *(const float4*)&As[c][8*ty + 4];
            float4 bv0 = *(const float4*)&Bs[c][8*tx];
            float4 bv1 = *(const float4*)&Bs[c][8*tx + 4];
            float av[8] = {av0.x,av0.y,av0.z,av0.w,av1.x,av1.y,av1.z,av1.w};
            float bv[8] = {bv0.x,bv0.y,bv0.z,bv0.w,bv1.x,bv1.y,bv1.z,bv1.w};
            #pragma unroll
            for (int rr = 0; rr < 8; ++rr)
                #pragma unroll
                for (int cc = 0; cc < 8; ++cc)
                    acc[rr][cc] = fmaf(av[rr], bv[cc], acc[rr][cc]);
        }
        __syncthreads();
    }

    #pragma unroll
    for (int rr = 0; rr < 8; ++rr) {
        float4 o0 = make_float4(acc[rr][0], acc[rr][1], acc[rr][2], acc[rr][3]);
        float4 o1 = make_float4(acc[rr][4], acc[rr][5], acc[rr][6], acc[rr][7]);
        float* dst = C + (size_t)(i0 + 8*ty + rr)*NSEQ + j0 + 8*tx;
        *(float4*)dst       = o0;
        *(float4*)(dst + 4) = o1;
    }
}

// ---------------------------------------------------------------------------
// Stage 3: LN(x) over d, final projection, gating, write output [i][j][c]
// ---------------------------------------------------------------------------
__global__ void __launch_bounds__(256) stage3_kernel(
    const float* __restrict__ lnow, const float* __restrict__ lnob,
    const float* __restrict__ zw,   const float* __restrict__ zb,
    float* __restrict__ out)
{
    extern __shared__ float sm[];
    float* s_x = sm;            // 64*129 (xn, later output staging 64*128)
    float* s_w = sm + 64*129;   // 128*129 (weights, later gate gather 64*129)

    const int tid = threadIdx.x;
    const int bi  = blockIdx.x;
    const int i   = bi >> 3;
    const int j0  = (bi & 7) * 64;
    const size_t rbase = (size_t)i*NSEQ + j0;

    // gather x[d][i][j0..j0+63] -> s_x[row][d]
    for (int idx = tid; idx < CDIM*64; idx += 256) {
        int dd = idx >> 6, rw = idx & 63;
        s_x[rw*129 + dd] = g_bufX[(size_t)dd*NN + rbase + rw];
    }
    __syncthreads();

    // layernorm over d
    {
        int rw = tid >> 2, l = tid & 3;
        float s = 0.f;
        for (int c = l; c < CDIM; c += 4) s += s_x[rw*129 + c];
        s += __shfl_down_sync(0xffffffffu, s, 1, 4);
        s += __shfl_down_sync(0xffffffffu, s, 2, 4);
        float mu = __shfl_sync(0xffffffffu, s, 0, 4) * (1.f/CDIM);
        float v = 0.f;
        for (int c = l; c < CDIM; c += 4) { float dlt = s_x[rw*129 + c] - mu; v = fmaf(dlt, dlt, v); }
        v += __shfl_down_sync(0xffffffffu, v, 1, 4);
        v += __shfl_down_sync(0xffffffffu, v, 2, 4);
        float rs = rsqrtf(__shfl_sync(0xffffffffu, v, 0, 4) * (1.f/CDIM) + 1e-5f);
        for (int c = l; c < CDIM; c += 4)
            s_x[rw*129 + c] = (s_x[rw*129 + c] - mu) * rs * lnow[c] + lnob[c];
    }
    __syncthreads();

    loadW(s_w, zw, tid);
    __syncthreads();

    const int tr = tid >> 4, tc = tid & 15;
    float acc[4][8];
    gemm_single(s_x, s_w, zb, tr, tc, acc);
    __syncthreads();

    // gather gate into s_w region: s_g[row][o]
    float* s_g = s_w;
    for (int idx = tid; idx < CDIM*64; idx += 256) {
        int o = idx >> 6, rw = idx & 63;
        s_g[rw*129 + o] = g_bufG[(size_t)o*NN + rbase + rw];
    }
    __syncthreads();

    // combine into output staging (reuse s_x, stride 128)
    #pragma unroll
    for (int rr = 0; rr < 4; ++rr)
        #pragma unroll
        for (int oo = 0; oo < 8; ++oo) {
            int o = tc + 16*oo, rw = 4*tr + rr;
            s_x[rw*CDIM + o] = acc[rr][oo] * s_g[rw*129 + o];
        }
    __syncthreads();

    // coalesced flush
    for (int idx = tid; idx < 64*CDIM; idx += 256) {
        int rw = idx >> 7;
        out[(rbase + rw)*CDIM + (idx & 127)] = s_x[idx];
    }
}

// ---------------------------------------------------------------------------
extern "C" void kernel_launch(void* const* d_in, const int* in_sizes, int n_in,
                              void* d_out, int out_size)
{
    const float* z    = (const float*)d_in[0];
    const float* mask = (const float*)d_in[1];
    const float* lniw = (const float*)d_in[2];
    const float* lnib = (const float*)d_in[3];
    const float* agw  = (const float*)d_in[4];
    const float* agb  = (const float*)d_in[5];
    const float* apw  = (const float*)d_in[6];
    const float* apb  = (const float*)d_in[7];
    const float* bgw  = (const float*)d_in[8];
    const float* bgb  = (const float*)d_in[9];
    const float* bpw  = (const float*)d_in[10];
    const float* bpb  = (const float*)d_in[11];
    const float* lnow = (const float*)d_in[12];
    const float* lnob = (const float*)d_in[13];
    const float* zw   = (const float*)d_in[14];
    const float* zb   = (const float*)d_in[15];
    const float* gww  = (const float*)d_in[16];
    const float* gwb  = (const float*)d_in[17];
    float* out = (float*)d_out;

    const int SMEM1 = (64*129 + 2*128*129 + 64) * (int)sizeof(float);   // ~165 KB
    const int SMEM3 = (64*129 + 128*129) * (int)sizeof(float);          // ~97 KB
    cudaFuncSetAttribute(stage1_kernel, cudaFuncAttributeMaxDynamicSharedMemorySize, SMEM1);
    cudaFuncSetAttribute(stage3_kernel, cudaFuncAttributeMaxDynamicSharedMemorySize, SMEM3);

    stage1_kernel<<<NN/64, 256, SMEM1>>>(z, mask, lniw, lnib,
                                         agw, agb, apw, apb,
                                         bgw, bgb, bpw, bpb, gww, gwb);
    stage2_kernel<<<dim3(4, 4, 128), 256>>>();
    stage3_kernel<<<NN/64, 256, SMEM3>>>(lnow, lnob, zw, zb, out);
}

// round 3
// speedup vs baseline: 2.4509x; 2.4509x over previous
#include <cuda_runtime.h>
#include <cuda_bf16.h>
#include <cstdint>

#define NSEQ 512
#define CDIM 128
#define NN (NSEQ*NSEQ)

// scratch, d-major fp32 (tf32-rounded where noted)
__device__ float g_bufA[(size_t)CDIM*NN];   // a[i,k,d] -> [d][i*512+k]  (tf32 bits)
__device__ float g_bufB[(size_t)CDIM*NN];   // b[k,j,d] -> [d][k*512+j]  (tf32 bits)
__device__ float g_bufG[(size_t)CDIM*NN];   // gate     -> [d][i*512+j]  (full fp32)
__device__ float g_bufX[(size_t)CDIM*NN];   // x        -> [d][i*512+j]  (full fp32)

// ---------------------------------------------------------------- helpers
__device__ __forceinline__ unsigned smem_u32(const void* p){
    return (unsigned)__cvta_generic_to_shared(p);
}
__device__ __forceinline__ float tf32r(float x){
    unsigned u;
    asm("cvt.rna.tf32.f32 %0, %1;\n" : "=r"(u) : "f"(x));
    return __uint_as_float(u);
}
__device__ __forceinline__ void mma_tf32(float c[4], const unsigned a[4], const unsigned b[2]){
    asm volatile("mma.sync.aligned.m16n8k8.row.col.f32.tf32.tf32.f32 "
        "{%0,%1,%2,%3}, {%4,%5,%6,%7}, {%8,%9}, {%0,%1,%2,%3};\n"
        : "+f"(c[0]),"+f"(c[1]),"+f"(c[2]),"+f"(c[3])
        : "r"(a[0]),"r"(a[1]),"r"(a[2]),"r"(a[3]), "r"(b[0]),"r"(b[1]));
}
__device__ __forceinline__ void cpa16(void* sdst, const void* gsrc){
    asm volatile("cp.async.cg.shared.global [%0], [%1], 16;\n"
        :: "r"(smem_u32(sdst)), "l"(gsrc));
}
__device__ __forceinline__ void cp_commit(){ asm volatile("cp.async.commit_group;\n"); }
template<int N> __device__ __forceinline__ void cp_wait(){
    asm volatile("cp.async.wait_group %0;\n" :: "n"(N));
}
__device__ __forceinline__ float sigmoidf_(float x){ return 1.f/(1.f+__expf(-x)); }
__device__ __forceinline__ unsigned U(const float* p){ return *(const unsigned*)p; }

// load 128x128 fp32 weight [o][c] -> smem [o][c] stride 132, tf32-rounded
__device__ __forceinline__ void loadW(float* dst, const float* __restrict__ W, int tid){
    #pragma unroll
    for (int i=0;i<16;++i){
        int cid = tid + i*256;
        int o = cid >> 5, c4 = (cid & 31)*4;
        float4 v = *(const float4*)(W + o*CDIM + c4);
        dst[o*132 + c4 + 0] = tf32r(v.x);
        dst[o*132 + c4 + 1] = tf32r(v.y);
        dst[o*132 + c4 + 2] = tf32r(v.z);
        dst[o*132 + c4 + 3] = tf32r(v.w);
    }
}

// ---------------------------------------------------------------------------
// Stage 1: LN(z) -> tf32, projections a,b (tf32 out), gate (fp32 out), d-major
// 64 rows per block. Warp w: rows m0=(w&3)*16, cols n0=(w>>2)*64.
// ---------------------------------------------------------------------------
__global__ void __launch_bounds__(256) stage1_kernel(
    const float* __restrict__ z,   const float* __restrict__ mask,
    const float* __restrict__ lnw, const float* __restrict__ lnb,
    const float* __restrict__ agw, const float* __restrict__ agb,
    const float* __restrict__ apw, const float* __restrict__ apb,
    const float* __restrict__ bgw, const float* __restrict__ bgb,
    const float* __restrict__ bpw, const float* __restrict__ bpb,
    const float* __restrict__ gw,  const float* __restrict__ gb)
{
    extern __shared__ char smraw[];
    float* s_zn = (float*)smraw;          // [64][132]
    float* s_w1 = s_zn + 64*132;          // [128][132]
    float* s_w2 = s_w1 + 128*132;         // [128][132]
    float* s_st = s_w2 + 128*132;         // [128][68]  staging (transposed out)
    float* s_msk= s_st + 128*68;          // [64]

    const int tid = threadIdx.x, lane = tid & 31, wid = tid >> 5;
    const int g = lane >> 2, tig = lane & 3;
    const int r0 = blockIdx.x * 64;

    if (tid < 64) s_msk[tid] = mask[r0 + tid];

    // LN: warp handles 8 rows
    {
        float4 wv = *(const float4*)(lnw + lane*4);
        float4 bv = *(const float4*)(lnb + lane*4);
        for (int it = 0; it < 8; ++it) {
            int row = wid*8 + it;
            float4 v = *(const float4*)(z + (size_t)(r0+row)*CDIM + lane*4);
            float s = v.x+v.y+v.z+v.w;
            #pragma unroll
            for (int o=16;o;o>>=1) s += __shfl_xor_sync(0xffffffffu, s, o);
            float mu = s * (1.f/CDIM);
            float dx=v.x-mu, dy=v.y-mu, dz=v.z-mu, dw=v.w-mu;
            float vv = dx*dx+dy*dy+dz*dz+dw*dw;
            #pragma unroll
            for (int o=16;o;o>>=1) vv += __shfl_xor_sync(0xffffffffu, vv, o);
            float rs = rsqrtf(vv*(1.f/CDIM) + 1e-5f);
            float* dstp = s_zn + row*132 + lane*4;
            dstp[0] = tf32r(dx*rs*wv.x+bv.x);
            dstp[1] = tf32r(dy*rs*wv.y+bv.y);
            dstp[2] = tf32r(dz*rs*wv.z+bv.z);
            dstp[3] = tf32r(dw*rs*wv.w+bv.w);
        }
    }

    const int m0 = (wid & 3)*16, n0 = (wid >> 2)*64;

    // gated pair: out = tf32( mask * sigmoid(zn@W1^T+b1) * (zn@W2^T+b2) )
    auto pair_pass = [&](const float* __restrict__ gbias, const float* __restrict__ pbias,
                         float* __restrict__ dstg) {
        float accG[8][4], accP[8][4];
        #pragma unroll
        for (int i=0;i<8;++i){
            #pragma unroll
            for (int j=0;j<4;++j){ accG[i][j]=0.f; accP[i][j]=0.f; }
        }
        #pragma unroll 4
        for (int ks=0; ks<16; ++ks) {
            unsigned a[4];
            const float* ab = s_zn + (m0+g)*132 + ks*8 + tig;
            a[0]=U(ab); a[1]=U(ab + 8*132); a[2]=U(ab + 4); a[3]=U(ab + 8*132 + 4);
            #pragma unroll
            for (int nt=0; nt<8; ++nt) {
                const float* b1p = s_w1 + (n0 + nt*8 + g)*132 + ks*8 + tig;
                const float* b2p = s_w2 + (n0 + nt*8 + g)*132 + ks*8 + tig;
                unsigned b1[2] = { U(b1p), U(b1p + 4) };
                unsigned b2[2] = { U(b2p), U(b2p + 4) };
                mma_tf32(accG[nt], a, b1);
                mma_tf32(accP[nt], a, b2);
            }
        }
        #pragma unroll
        for (int nt=0; nt<8; ++nt) {
            #pragma unroll
            for (int j=0;j<4;++j) {
                int r = m0 + g + ((j>>1)<<3);
                int o = n0 + nt*8 + tig*2 + (j&1);
                float gv = accG[nt][j] + __ldg(gbias + o);
                float pv = accP[nt][j] + __ldg(pbias + o);
                s_st[o*68 + r] = tf32r(s_msk[r] * sigmoidf_(gv) * pv);
            }
        }
        __syncthreads();
        #pragma unroll
        for (int i=0;i<8;++i){
            int cid = tid + i*256; int dd = cid>>4; int rc = (cid&15)*4;
            *(float4*)(dstg + (size_t)dd*NN + r0 + rc) = *(const float4*)(s_st + dd*68 + rc);
        }
        __syncthreads();
    };

    loadW(s_w1, agw, tid);
    loadW(s_w2, apw, tid);
    __syncthreads();
    pair_pass(agb, apb, g_bufA);

    loadW(s_w1, bgw, tid);
    loadW(s_w2, bpw, tid);
    __syncthreads();
    pair_pass(bgb, bpb, g_bufB);

    // gate = sigmoid(zn@gw^T + gb), full fp32 out
    loadW(s_w1, gw, tid);
    __syncthreads();
    {
        float accG[8][4];
        #pragma unroll
        for (int i=0;i<8;++i){
            #pragma unroll
            for (int j=0;j<4;++j) accG[i][j]=0.f;
        }
        #pragma unroll 4
        for (int ks=0; ks<16; ++ks) {
            unsigned a[4];
            const float* ab = s_zn + (m0+g)*132 + ks*8 + tig;
            a[0]=U(ab); a[1]=U(ab + 8*132); a[2]=U(ab + 4); a[3]=U(ab + 8*132 + 4);
            #pragma unroll
            for (int nt=0; nt<8; ++nt) {
                const float* bp = s_w1 + (n0 + nt*8 + g)*132 + ks*8 + tig;
                unsigned b[2] = { U(bp), U(bp + 4) };
                mma_tf32(accG[nt], a, b);
            }
        }
        #pragma unroll
        for (int nt=0; nt<8; ++nt) {
            #pragma unroll
            for (int j=0;j<4;++j) {
                int r = m0 + g + ((j>>1)<<3);
                int o = n0 + nt*8 + tig*2 + (j&1);
                s_st[o*68 + r] = sigmoidf_(accG[nt][j] + __ldg(gb + o));
            }
        }
        __syncthreads();
        #pragma unroll
        for (int i=0;i<8;++i){
            int cid = tid + i*256; int dd = cid>>4; int rc = (cid&15)*4;
            *(float4*)(g_bufG + (size_t)dd*NN + r0 + rc) = *(const float4*)(s_st + dd*68 + rc);
        }
    }
}

// ---------------------------------------------------------------------------
// Stage 2: per-d tf32 GEMM x[d] = a[d] @ b[d]. 128x128 tile, kt=32, cp.async 2-buf
// ---------------------------------------------------------------------------
__global__ void __launch_bounds__(256) stage2_kernel()
{
    extern __shared__ char smraw[];
    float* As = (float*)smraw;            // [2][128*36]  [i][k]
    float* Bs = As + 2*128*36;            // [2][32*132]  [k][j]

    const int d = blockIdx.z;
    const float* gA = g_bufA + (size_t)d*NN;
    const float* gB = g_bufB + (size_t)d*NN;
    float* gC = g_bufX + (size_t)d*NN;
    const int i0 = blockIdx.y*128, j0 = blockIdx.x*128;
    const int tid = threadIdx.x, lane = tid&31, wid = tid>>5;
    const int g = lane >> 2, tig = lane & 3;
    const int wm = wid & 3, wn = wid >> 2;    // warp tile 32(m) x 64(n)

    float acc[2][8][4];
    #pragma unroll
    for (int a=0;a<2;++a){
        #pragma unroll
        for(int b=0;b<8;++b){
            #pragma unroll
            for(int c=0;c<4;++c) acc[a][b][c]=0.f;
        }
    }

    auto load_tile = [&](int kt, int buf){
        float* Ab = As + buf*128*36;
        float* Bb = Bs + buf*32*132;
        #pragma unroll
        for (int i=0;i<4;++i){
            int cid = tid + i*256;
            int r = cid>>3, kc = (cid&7)*4;
            cpa16(Ab + r*36 + kc, gA + (size_t)(i0+r)*NSEQ + kt + kc);
        }
        #pragma unroll
        for (int i=0;i<4;++i){
            int cid = tid + i*256;
            int kk = cid>>5, jc = (cid&31)*4;
            cpa16(Bb + kk*132 + jc, gB + (size_t)(kt+kk)*NSEQ + j0 + jc);
        }
        cp_commit();
    };

    load_tile(0, 0);
    int buf = 0;
    for (int t=0; t<16; ++t) {
        if (t < 15) { load_tile((t+1)*32, buf^1); cp_wait<1>(); }
        else        { cp_wait<0>(); }
        __syncthreads();
        const float* Ab = As + buf*128*36;
        const float* Bb = Bs + buf*32*132;
        #pragma unroll
        for (int ks=0; ks<4; ++ks) {
            unsigned a[2][4];
            #pragma unroll
            for (int mt=0; mt<2; ++mt) {
                const float* ap = Ab + (wm*32 + mt*16 + g)*36 + ks*8 + tig;
                a[mt][0]=U(ap); a[mt][1]=U(ap + 8*36); a[mt][2]=U(ap + 4); a[mt][3]=U(ap + 8*36 + 4);
            }
            #pragma unroll
            for (int nt=0; nt<8; ++nt) {
                const float* bp = Bb + (ks*8 + tig)*132 + wn*64 + nt*8 + g;
                unsigned b[2] = { U(bp), U(bp + 4*132) };
                mma_tf32(acc[0][nt], a[0], b);
                mma_tf32(acc[1][nt], a[1], b);
            }
        }
        __syncthreads();
        buf ^= 1;
    }

    #pragma unroll
    for (int mt=0; mt<2; ++mt){
        #pragma unroll
        for (int nt=0; nt<8; ++nt) {
            int r = i0 + wm*32 + mt*16 + g;
            int c = j0 + wn*64 + nt*8 + tig*2;
            *(float2*)(gC + (size_t)r*NSEQ + c)     = make_float2(acc[mt][nt][0], acc[mt][nt][1]);
            *(float2*)(gC + (size_t)(r+8)*NSEQ + c) = make_float2(acc[mt][nt][2], acc[mt][nt][3]);
        }
    }
}

// ---------------------------------------------------------------------------
// Stage 3: gather x, LN -> tf32, final projection, gate multiply, store
// 128 rows per block; warp w: rows m0=w*16, all 128 cols.
// ---------------------------------------------------------------------------
__global__ void __launch_bounds__(256) stage3_kernel(
    const float* __restrict__ lnow, const float* __restrict__ lnob,
    const float* __restrict__ zw,   const float* __restrict__ zb,
    float* __restrict__ out)
{
    extern __shared__ char smraw[];
    float* s_x  = (float*)smraw;          // [128][133]  x, then gate
    float* s_xn = s_x + 128*133;          // [128][132]  tf32
    float* s_w  = s_xn + 128*132;         // [128][132]  tf32

    const int tid = threadIdx.x, lane = tid&31, wid = tid>>5;
    const int g = lane >> 2, tig = lane & 3;
    const int bi = blockIdx.x;
    const int ti = bi >> 2, j0 = (bi & 3)*128;
    const size_t rbase = (size_t)ti*NSEQ + j0;

    // gather x[d][rbase + rc] -> s_x[row][d]
    #pragma unroll
    for (int it=0; it<16; ++it){
        int cid = tid + it*256; int dd = cid>>5; int rc = (cid&31)*4;
        float4 v = *(const float4*)(g_bufX + (size_t)dd*NN + rbase + rc);
        s_x[(rc+0)*133 + dd] = v.x;
        s_x[(rc+1)*133 + dd] = v.y;
        s_x[(rc+2)*133 + dd] = v.z;
        s_x[(rc+3)*133 + dd] = v.w;
    }
    __syncthreads();

    // LN over d -> tf32
    {
        float4 wv = *(const float4*)(lnow + lane*4);
        float4 bv = *(const float4*)(lnob + lane*4);
        for (int it=0; it<16; ++it){
            int row = wid*16 + it;
            const float* rp = s_x + row*133 + lane*4;
            float e0=rp[0], e1=rp[1], e2=rp[2], e3=rp[3];
            float s = e0+e1+e2+e3;
            #pragma unroll
            for (int o=16;o;o>>=1) s += __shfl_xor_sync(0xffffffffu, s, o);
            float mu = s*(1.f/CDIM);
            float dx=e0-mu, dy=e1-mu, dz=e2-mu, dw=e3-mu;
            float vv = dx*dx+dy*dy+dz*dz+dw*dw;
            #pragma unroll
            for (int o=16;o;o>>=1) vv += __shfl_xor_sync(0xffffffffu, vv, o);
            float rs = rsqrtf(vv*(1.f/CDIM)+1e-5f);
            float* dp = s_xn + row*132 + lane*4;
            dp[0] = tf32r(dx*rs*wv.x+bv.x);
            dp[1] = tf32r(dy*rs*wv.y+bv.y);
            dp[2] = tf32r(dz*rs*wv.z+bv.z);
            dp[3] = tf32r(dw*rs*wv.w+bv.w);
        }
    }
    __syncthreads();

    // weights + gate gather (gate overwrites s_x)
    loadW(s_w, zw, tid);
    #pragma unroll
    for (int it=0; it<16; ++it){
        int cid = tid + it*256; int dd = cid>>5; int rc = (cid&31)*4;
        float4 v = *(const float4*)(g_bufG + (size_t)dd*NN + rbase + rc);
        s_x[(rc+0)*133 + dd] = v.x;
        s_x[(rc+1)*133 + dd] = v.y;
        s_x[(rc+2)*133 + dd] = v.z;
        s_x[(rc+3)*133 + dd] = v.w;
    }
    __syncthreads();

    const int m0 = wid*16;
    float acc[16][4];
    #pragma unroll
    for (int i=0;i<16;++i){
        #pragma unroll
        for(int j=0;j<4;++j) acc[i][j]=0.f;
    }
    #pragma unroll 2
    for (int ks=0; ks<16; ++ks) {
        unsigned a[4];
        const float* ap = s_xn + (m0+g)*132 + ks*8 + tig;
        a[0]=U(ap); a[1]=U(ap + 8*132); a[2]=U(ap + 4); a[3]=U(ap + 8*132 + 4);
        #pragma unroll
        for (int nt=0; nt<16; ++nt) {
            const float* bp = s_w + (nt*8 + g)*132 + ks*8 + tig;
            unsigned b[2] = { U(bp), U(bp + 4) };
            mma_tf32(acc[nt], a, b);
        }
    }

    #pragma unroll
    for (int nt=0; nt<16; ++nt){
        #pragma unroll
        for (int jp=0; jp<2; ++jp){
            int r = m0 + g + jp*8;
            int o = nt*8 + tig*2;
            float v0 = acc[nt][jp*2+0] + __ldg(zb + o);
            float v1 = acc[nt][jp*2+1] + __ldg(zb + o + 1);
            float g0 = s_x[r*133 + o];
            float g1 = s_x[r*133 + o + 1];
            *(float2*)(out + (rbase + r)*CDIM + o) = make_float2(v0*g0, v1*g1);
        }
    }
}

// ---------------------------------------------------------------------------
extern "C" void kernel_launch(void* const* d_in, const int* in_sizes, int n_in,
                              void* d_out, int out_size)
{
    const float* z    = (const float*)d_in[0];
    const float* mask = (const float*)d_in[1];
    const float* lniw = (const float*)d_in[2];
    const float* lnib = (const float*)d_in[3];
    const float* agw  = (const float*)d_in[4];
    const float* agb  = (const float*)d_in[5];
    const float* apw  = (const float*)d_in[6];
    const float* apb  = (const float*)d_in[7];
    const float* bgw  = (const float*)d_in[8];
    const float* bgb  = (const float*)d_in[9];
    const float* bpw  = (const float*)d_in[10];
    const float* bpb  = (const float*)d_in[11];
    const float* lnow = (const float*)d_in[12];
    const float* lnob = (const float*)d_in[13];
    const float* zw   = (const float*)d_in[14];
    const float* zb   = (const float*)d_in[15];
    const float* gww  = (const float*)d_in[16];
    const float* gwb  = (const float*)d_in[17];
    float* out = (float*)d_out;

    const int SMEM1 = (64*132 + 2*128*132 + 128*68 + 64) * 4;      // ~199 KB
    const int SMEM2 = (2*128*36 + 2*32*132) * 4;                   // ~69 KB
    const int SMEM3 = (128*133 + 2*128*132) * 4;                   // ~199 KB
    cudaFuncSetAttribute(stage1_kernel, cudaFuncAttributeMaxDynamicSharedMemorySize, SMEM1);
    cudaFuncSetAttribute(stage2_kernel, cudaFuncAttributeMaxDynamicSharedMemorySize, SMEM2);
    cudaFuncSetAttribute(stage3_kernel, cudaFuncAttributeMaxDynamicSharedMemorySize, SMEM3);

    stage1_kernel<<<NN/64, 256, SMEM1>>>(z, mask, lniw, lnib,
                                         agw, agb, apw, apb,
                                         bgw, bgb, bpw, bpb, gww, gwb);
    stage2_kernel<<<dim3(4,4,128), 256, SMEM2>>>();
    stage3_kernel<<<NN/128, 256, SMEM3>>>(lnow, lnob, zw, zb, out);
}

// round 4
// speedup vs baseline: 2.6979x; 1.1008x over previous
#include <cuda_runtime.h>
#include <cuda_bf16.h>
#include <cstdint>

#define NSEQ 512
#define CDIM 128
#define NN (NSEQ*NSEQ)

// scratch, d-major fp32 (tf32-rounded where noted)
__device__ float g_bufA[(size_t)CDIM*NN];   // a[i,k,d] -> [d][i*512+k]  (tf32 bits)
__device__ float g_bufB[(size_t)CDIM*NN];   // b[k,j,d] -> [d][k*512+j]  (tf32 bits)
__device__ float g_bufG[(size_t)CDIM*NN];   // gate     -> [d][i*512+j]  (full fp32)
__device__ float g_bufX[(size_t)CDIM*NN];   // x        -> [d][i*512+j]  (full fp32)

// ---------------------------------------------------------------- helpers
__device__ __forceinline__ unsigned smem_u32(const void* p){
    return (unsigned)__cvta_generic_to_shared(p);
}
__device__ __forceinline__ float tf32r(float x){
    unsigned u;
    asm("cvt.rna.tf32.f32 %0, %1;\n" : "=r"(u) : "f"(x));
    return __uint_as_float(u);
}
__device__ __forceinline__ unsigned tf32b(float x){
    unsigned u;
    asm("cvt.rna.tf32.f32 %0, %1;\n" : "=r"(u) : "f"(x));
    return u;
}
__device__ __forceinline__ void mma_tf32(float c[4], const unsigned a[4], const unsigned b[2]){
    asm volatile("mma.sync.aligned.m16n8k8.row.col.f32.tf32.tf32.f32 "
        "{%0,%1,%2,%3}, {%4,%5,%6,%7}, {%8,%9}, {%0,%1,%2,%3};\n"
        : "+f"(c[0]),"+f"(c[1]),"+f"(c[2]),"+f"(c[3])
        : "r"(a[0]),"r"(a[1]),"r"(a[2]),"r"(a[3]), "r"(b[0]),"r"(b[1]));
}
__device__ __forceinline__ void cpa16(void* sdst, const void* gsrc){
    asm volatile("cp.async.cg.shared.global [%0], [%1], 16;\n"
        :: "r"(smem_u32(sdst)), "l"(gsrc));
}
__device__ __forceinline__ void cp_commit(){ asm volatile("cp.async.commit_group;\n"); }
template<int N> __device__ __forceinline__ void cp_wait(){
    asm volatile("cp.async.wait_group %0;\n" :: "n"(N));
}
__device__ __forceinline__ float sigmoidf_(float x){ return 1.f/(1.f+__expf(-x)); }
__device__ __forceinline__ unsigned U(const float* p){ return *(const unsigned*)p; }

// ---------------------------------------------------------------------------
// Stage 1 (flipped GEMM): out[o][r] = W[o][:] . zn[r][:]
//   A-operand = W (fragments via __ldg from L2), B-operand = zn (smem, k-permuted)
//   Direct d-major global stores. 64 rows/block, smem = zn only.
//   Warp w: o-tile m0 = w*16 (all 8 warps cover 128 channels), all 64 rows.
// k-permutation within 8-groups: logical k (kg=k&7) -> slot (kg<4 ? 2kg : 2(kg-4)+1)
// so (k, k+4) pairs are contiguous -> LDS.64 for B-fragments.
// ---------------------------------------------------------------------------
__global__ void __launch_bounds__(256,2) stage1_kernel(
    const float* __restrict__ z,   const float* __restrict__ mask,
    const float* __restrict__ lnw, const float* __restrict__ lnb,
    const float* __restrict__ agw, const float* __restrict__ agb,
    const float* __restrict__ apw, const float* __restrict__ apb,
    const float* __restrict__ bgw, const float* __restrict__ bgb,
    const float* __restrict__ bpw, const float* __restrict__ bpb,
    const float* __restrict__ gw,  const float* __restrict__ gb)
{
    __shared__ float s_zn[64*136];
    __shared__ float s_msk[64];

    const int tid = threadIdx.x, lane = tid & 31, wid = tid >> 5;
    const int g = lane >> 2, tig = lane & 3;
    const int r0 = blockIdx.x * 64;

    if (tid < 64) s_msk[tid] = mask[r0 + tid];

    // LN: warp handles 8 rows; write tf32 zn with k-permutation, stride 136
    {
        float4 wv = *(const float4*)(lnw + lane*4);
        float4 bv = *(const float4*)(lnb + lane*4);
        for (int it = 0; it < 8; ++it) {
            int row = wid*8 + it;
            float4 v = *(const float4*)(z + (size_t)(r0+row)*CDIM + lane*4);
            float s = v.x+v.y+v.z+v.w;
            #pragma unroll
            for (int o=16;o;o>>=1) s += __shfl_xor_sync(0xffffffffu, s, o);
            float mu = s * (1.f/CDIM);
            float dx=v.x-mu, dy=v.y-mu, dz=v.z-mu, dw=v.w-mu;
            float vv = dx*dx+dy*dy+dz*dz+dw*dw;
            #pragma unroll
            for (int o=16;o;o>>=1) vv += __shfl_xor_sync(0xffffffffu, vv, o);
            float rs = rsqrtf(vv*(1.f/CDIM) + 1e-5f);
            // c = lane*4 + q  -> group = lane>>1, slot = 2q + (lane&1)
            float* dstp = s_zn + row*136 + (lane>>1)*8 + (lane&1);
            dstp[0] = tf32r(dx*rs*wv.x+bv.x);
            dstp[2] = tf32r(dy*rs*wv.y+bv.y);
            dstp[4] = tf32r(dz*rs*wv.z+bv.z);
            dstp[6] = tf32r(dw*rs*wv.w+bv.w);
        }
    }
    __syncthreads();

    const int m0 = wid*16;          // this warp's 16 output channels

    // gated pair: out = tf32( mask * sigmoid(W1.zn + b1) * (W2.zn + b2) ), d-major
    auto pair_pass = [&](const float* __restrict__ W1, const float* __restrict__ b1v,
                         const float* __restrict__ W2, const float* __restrict__ b2v,
                         float* __restrict__ dst) {
        float accG[8][4], accP[8][4];
        #pragma unroll
        for (int i=0;i<8;++i){
            #pragma unroll
            for (int j=0;j<4;++j){ accG[i][j]=0.f; accP[i][j]=0.f; }
        }
        const float bG0 = __ldg(b1v+m0+g), bG8 = __ldg(b1v+m0+g+8);
        const float bP0 = __ldg(b2v+m0+g), bP8 = __ldg(b2v+m0+g+8);

        #pragma unroll 4
        for (int ks=0; ks<16; ++ks) {
            const float* w1p = W1 + (size_t)(m0+g)*CDIM + ks*8 + tig;
            const float* w2p = W2 + (size_t)(m0+g)*CDIM + ks*8 + tig;
            unsigned a1[4], a2[4];
            a1[0]=tf32b(__ldg(w1p));            a1[1]=tf32b(__ldg(w1p+8*CDIM));
            a1[2]=tf32b(__ldg(w1p+4));          a1[3]=tf32b(__ldg(w1p+8*CDIM+4));
            a2[0]=tf32b(__ldg(w2p));            a2[1]=tf32b(__ldg(w2p+8*CDIM));
            a2[2]=tf32b(__ldg(w2p+4));          a2[3]=tf32b(__ldg(w2p+8*CDIM+4));
            #pragma unroll
            for (int nt=0; nt<8; ++nt) {
                float2 bb = *(const float2*)(s_zn + (nt*8+g)*136 + ks*8 + 2*tig);
                unsigned b[2] = { U(&bb.x), U(&bb.y) };
                mma_tf32(accG[nt], a1, b);
                mma_tf32(accP[nt], a2, b);
            }
        }
        #pragma unroll
        for (int nt=0; nt<8; ++nt) {
            const int rr = nt*8 + tig*2;
            const float mk0 = s_msk[rr], mk1 = s_msk[rr+1];
            float2 o0, o1;
            o0.x = tf32r(mk0 * sigmoidf_(accG[nt][0]+bG0) * (accP[nt][0]+bP0));
            o0.y = tf32r(mk1 * sigmoidf_(accG[nt][1]+bG0) * (accP[nt][1]+bP0));
            o1.x = tf32r(mk0 * sigmoidf_(accG[nt][2]+bG8) * (accP[nt][2]+bP8));
            o1.y = tf32r(mk1 * sigmoidf_(accG[nt][3]+bG8) * (accP[nt][3]+bP8));
            *(float2*)(dst + (size_t)(m0+g)*NN   + r0 + rr) = o0;
            *(float2*)(dst + (size_t)(m0+g+8)*NN + r0 + rr) = o1;
        }
    };

    pair_pass(agw, agb, apw, apb, g_bufA);
    pair_pass(bgw, bgb, bpw, bpb, g_bufB);

    // gate = sigmoid(gw.zn + gb), full fp32, d-major
    {
        float acc[8][4];
        #pragma unroll
        for (int i=0;i<8;++i){
            #pragma unroll
            for (int j=0;j<4;++j) acc[i][j]=0.f;
        }
        const float bg0 = __ldg(gb+m0+g), bg8 = __ldg(gb+m0+g+8);
        #pragma unroll 4
        for (int ks=0; ks<16; ++ks) {
            const float* wp = gw + (size_t)(m0+g)*CDIM + ks*8 + tig;
            unsigned a[4];
            a[0]=tf32b(__ldg(wp));       a[1]=tf32b(__ldg(wp+8*CDIM));
            a[2]=tf32b(__ldg(wp+4));     a[3]=tf32b(__ldg(wp+8*CDIM+4));
            #pragma unroll
            for (int nt=0; nt<8; ++nt) {
                float2 bb = *(const float2*)(s_zn + (nt*8+g)*136 + ks*8 + 2*tig);
                unsigned b[2] = { U(&bb.x), U(&bb.y) };
                mma_tf32(acc[nt], a, b);
            }
        }
        #pragma unroll
        for (int nt=0; nt<8; ++nt) {
            const int rr = nt*8 + tig*2;
            float2 o0, o1;
            o0.x = sigmoidf_(acc[nt][0]+bg0);
            o0.y = sigmoidf_(acc[nt][1]+bg0);
            o1.x = sigmoidf_(acc[nt][2]+bg8);
            o1.y = sigmoidf_(acc[nt][3]+bg8);
            *(float2*)(g_bufG + (size_t)(m0+g)*NN   + r0 + rr) = o0;
            *(float2*)(g_bufG + (size_t)(m0+g+8)*NN + r0 + rr) = o1;
        }
    }
}

// ---------------------------------------------------------------------------
// Stage 2: per-d tf32 GEMM x[d] = a[d] @ b[d]. 128x128 tile, kt=32, cp.async 2-buf
// ---------------------------------------------------------------------------
__global__ void __launch_bounds__(256) stage2_kernel()
{
    extern __shared__ char smraw[];
    float* As = (float*)smraw;            // [2][128*36]  [i][k]
    float* Bs = As + 2*128*36;            // [2][32*132]  [k][j]

    const int d = blockIdx.z;
    const float* gA = g_bufA + (size_t)d*NN;
    const float* gB = g_bufB + (size_t)d*NN;
    float* gC = g_bufX + (size_t)d*NN;
    const int i0 = blockIdx.y*128, j0 = blockIdx.x*128;
    const int tid = threadIdx.x, lane = tid&31, wid = tid>>5;
    const int g = lane >> 2, tig = lane & 3;
    const int wm = wid & 3, wn = wid >> 2;    // warp tile 32(m) x 64(n)

    float acc[2][8][4];
    #pragma unroll
    for (int a=0;a<2;++a){
        #pragma unroll
        for(int b=0;b<8;++b){
            #pragma unroll
            for(int c=0;c<4;++c) acc[a][b][c]=0.f;
        }
    }

    auto load_tile = [&](int kt, int buf){
        float* Ab = As + buf*128*36;
        float* Bb = Bs + buf*32*132;
        #pragma unroll
        for (int i=0;i<4;++i){
            int cid = tid + i*256;
            int r = cid>>3, kc = (cid&7)*4;
            cpa16(Ab + r*36 + kc, gA + (size_t)(i0+r)*NSEQ + kt + kc);
        }
        #pragma unroll
        for (int i=0;i<4;++i){
            int cid = tid + i*256;
            int kk = cid>>5, jc = (cid&31)*4;
            cpa16(Bb + kk*132 + jc, gB + (size_t)(kt+kk)*NSEQ + j0 + jc);
        }
        cp_commit();
    };

    load_tile(0, 0);
    int buf = 0;
    for (int t=0; t<16; ++t) {
        if (t < 15) { load_tile((t+1)*32, buf^1); cp_wait<1>(); }
        else        { cp_wait<0>(); }
        __syncthreads();
        const float* Ab = As + buf*128*36;
        const float* Bb = Bs + buf*32*132;
        #pragma unroll
        for (int ks=0; ks<4; ++ks) {
            unsigned a[2][4];
            #pragma unroll
            for (int mt=0; mt<2; ++mt) {
                const float* ap = Ab + (wm*32 + mt*16 + g)*36 + ks*8 + tig;
                a[mt][0]=U(ap); a[mt][1]=U(ap + 8*36); a[mt][2]=U(ap + 4); a[mt][3]=U(ap + 8*36 + 4);
            }
            #pragma unroll
            for (int nt=0; nt<8; ++nt) {
                const float* bp = Bb + (ks*8 + tig)*132 + wn*64 + nt*8 + g;
                unsigned b[2] = { U(bp), U(bp + 4*132) };
                mma_tf32(acc[0][nt], a[0], b);
                mma_tf32(acc[1][nt], a[1], b);
            }
        }
        __syncthreads();
        buf ^= 1;
    }

    #pragma unroll
    for (int mt=0; mt<2; ++mt){
        #pragma unroll
        for (int nt=0; nt<8; ++nt) {
            int r = i0 + wm*32 + mt*16 + g;
            int c = j0 + wn*64 + nt*8 + tig*2;
            *(float2*)(gC + (size_t)r*NSEQ + c)     = make_float2(acc[mt][nt][0], acc[mt][nt][1]);
            *(float2*)(gC + (size_t)(r+8)*NSEQ + c) = make_float2(acc[mt][nt][2], acc[mt][nt][3]);
        }
    }
}

// ---------------------------------------------------------------------------
// Stage 3: gather x, LN -> tf32 (k-permuted smem), final projection with
// weight fragments via __ldg, gate multiply, store. 64 rows/block.
// Warp w: rows m0=(w&3)*16, output cols n0=(w>>2)*64.
// ---------------------------------------------------------------------------
__global__ void __launch_bounds__(256,2) stage3_kernel(
    const float* __restrict__ lnow, const float* __restrict__ lnob,
    const float* __restrict__ zw,   const float* __restrict__ zb,
    float* __restrict__ out)
{
    extern __shared__ char smraw[];
    float* s_x  = (float*)smraw;          // [64][133]  x, then gate, [r][d]
    float* s_xn = s_x + 64*133;           // [64][136]  tf32, k-permuted

    const int tid = threadIdx.x, lane = tid&31, wid = tid>>5;
    const int g = lane >> 2, tig = lane & 3;
    const int bi = blockIdx.x;
    const int ti = bi >> 3, j0 = (bi & 7)*64;
    const size_t rbase = (size_t)ti*NSEQ + j0;

    // gather x[d][rbase + rc] -> s_x[r][d]
    #pragma unroll
    for (int it=0; it<8; ++it){
        int cid = tid + it*256; int dd = cid>>4; int rc = (cid&15)*4;
        float4 v = *(const float4*)(g_bufX + (size_t)dd*NN + rbase + rc);
        s_x[(rc+0)*133 + dd] = v.x;
        s_x[(rc+1)*133 + dd] = v.y;
        s_x[(rc+2)*133 + dd] = v.z;
        s_x[(rc+3)*133 + dd] = v.w;
    }
    __syncthreads();

    // LN over d -> tf32, k-permuted, stride 136
    {
        float4 wv = *(const float4*)(lnow + lane*4);
        float4 bv = *(const float4*)(lnob + lane*4);
        for (int it=0; it<8; ++it){
            int row = wid*8 + it;
            const float* rp = s_x + row*133 + lane*4;
            float e0=rp[0], e1=rp[1], e2=rp[2], e3=rp[3];
            float s = e0+e1+e2+e3;
            #pragma unroll
            for (int o=16;o;o>>=1) s += __shfl_xor_sync(0xffffffffu, s, o);
            float mu = s*(1.f/CDIM);
            float dx=e0-mu, dy=e1-mu, dz=e2-mu, dw=e3-mu;
            float vv = dx*dx+dy*dy+dz*dz+dw*dw;
            #pragma unroll
            for (int o=16;o;o>>=1) vv += __shfl_xor_sync(0xffffffffu, vv, o);
            float rs = rsqrtf(vv*(1.f/CDIM)+1e-5f);
            float* dp = s_xn + row*136 + (lane>>1)*8 + (lane&1);
            dp[0] = tf32r(dx*rs*wv.x+bv.x);
            dp[2] = tf32r(dy*rs*wv.y+bv.y);
            dp[4] = tf32r(dz*rs*wv.z+bv.z);
            dp[6] = tf32r(dw*rs*wv.w+bv.w);
        }
    }
    __syncthreads();

    // gate gather overwrites s_x
    #pragma unroll
    for (int it=0; it<8; ++it){
        int cid = tid + it*256; int dd = cid>>4; int rc = (cid&15)*4;
        float4 v = *(const float4*)(g_bufG + (size_t)dd*NN + rbase + rc);
        s_x[(rc+0)*133 + dd] = v.x;
        s_x[(rc+1)*133 + dd] = v.y;
        s_x[(rc+2)*133 + dd] = v.z;
        s_x[(rc+3)*133 + dd] = v.w;
    }
    __syncthreads();

    const int m0 = (wid&3)*16, n0 = (wid>>2)*64;
    float acc[8][4];
    #pragma unroll
    for (int i=0;i<8;++i){
        #pragma unroll
        for(int j=0;j<4;++j) acc[i][j]=0.f;
    }
    #pragma unroll 4
    for (int ks=0; ks<16; ++ks) {
        unsigned a[4];
        float2 p0 = *(const float2*)(s_xn + (m0+g)*136   + ks*8 + 2*tig);
        float2 p1 = *(const float2*)(s_xn + (m0+g+8)*136 + ks*8 + 2*tig);
        a[0]=U(&p0.x); a[1]=U(&p1.x); a[2]=U(&p0.y); a[3]=U(&p1.y);
        #pragma unroll
        for (int nt=0; nt<8; ++nt) {
            const float* wp = zw + (size_t)(n0+nt*8+g)*CDIM + ks*8 + tig;
            unsigned b[2] = { tf32b(__ldg(wp)), tf32b(__ldg(wp+4)) };
            mma_tf32(acc[nt], a, b);
        }
    }

    #pragma unroll
    for (int nt=0; nt<8; ++nt){
        const int o = n0 + nt*8 + tig*2;
        const float zb0 = __ldg(zb+o), zb1 = __ldg(zb+o+1);
        {
            int r = m0 + g;
            float2 ov = make_float2((acc[nt][0]+zb0) * s_x[r*133+o],
                                    (acc[nt][1]+zb1) * s_x[r*133+o+1]);
            *(float2*)(out + (rbase + r)*CDIM + o) = ov;
        }
        {
            int r = m0 + g + 8;
            float2 ov = make_float2((acc[nt][2]+zb0) * s_x[r*133+o],
                                    (acc[nt][3]+zb1) * s_x[r*133+o+1]);
            *(float2*)(out + (rbase + r)*CDIM + o) = ov;
        }
    }
}

// ---------------------------------------------------------------------------
extern "C" void kernel_launch(void* const* d_in, const int* in_sizes, int n_in,
                              void* d_out, int out_size)
{
    const float* z    = (const float*)d_in[0];
    const float* mask = (const float*)d_in[1];
    const float* lniw = (const float*)d_in[2];
    const float* lnib = (const float*)d_in[3];
    const float* agw  = (const float*)d_in[4];
    const float* agb  = (const float*)d_in[5];
    const float* apw  = (const float*)d_in[6];
    const float* apb  = (const float*)d_in[7];
    const float* bgw  = (const float*)d_in[8];
    const float* bgb  = (const float*)d_in[9];
    const float* bpw  = (const float*)d_in[10];
    const float* bpb  = (const float*)d_in[11];
    const float* lnow = (const float*)d_in[12];
    const float* lnob = (const float*)d_in[13];
    const float* zw   = (const float*)d_in[14];
    const float* zb   = (const float*)d_in[15];
    const float* gww  = (const float*)d_in[16];
    const float* gwb  = (const float*)d_in[17];
    float* out = (float*)d_out;

    const int SMEM2 = (2*128*36 + 2*32*132) * 4;   // ~69 KB
    const int SMEM3 = (64*133 + 64*136) * 4;       // ~69 KB
    cudaFuncSetAttribute(stage2_kernel, cudaFuncAttributeMaxDynamicSharedMemorySize, SMEM2);
    cudaFuncSetAttribute(stage3_kernel, cudaFuncAttributeMaxDynamicSharedMemorySize, SMEM3);

    stage1_kernel<<<NN/64, 256>>>(z, mask, lniw, lnib,
                                  agw, agb, apw, apb,
                                  bgw, bgb, bpw, bpb, gww, gwb);
    stage2_kernel<<<dim3(4,4,128), 256, SMEM2>>>();
    stage3_kernel<<<NN/64, 256, SMEM3>>>(lnow, lnob, zw, zb, out);
}

// round 5
// speedup vs baseline: 4.2512x; 1.5758x over previous
#include <cuda_runtime.h>
#include <cuda_bf16.h>
#include <cstdint>

#define NSEQ 512
#define CDIM 128
#define NN (NSEQ*NSEQ)

// scratch, d-major fp32 (tf32-rounded where noted)
__device__ float g_bufA[(size_t)CDIM*NN];   // a[i,k,d] -> [d][i*512+k]  (tf32 bits)
__device__ float g_bufB[(size_t)CDIM*NN];   // b[k,j,d] -> [d][k*512+j]  (tf32 bits)
__device__ float g_bufG[(size_t)CDIM*NN];   // gate     -> [d][i*512+j]  (full fp32)
__device__ float g_bufX[(size_t)CDIM*NN];   // x        -> [d][i*512+j]  (full fp32)

// prepacked weights, mma-fragment order, tf32-prerounded
// A-pack (stage1): [m][ct][ks][lane] uint4 ; m: 0=agw 1=apw 2=bgw 3=bpw 4=gw
__device__ uint4 g_wpA[5*4096];
// B-pack (stage3, zw): [j8][ks][lane] uint2
__device__ uint2 g_wpB[8192];

// ---------------------------------------------------------------- helpers
__device__ __forceinline__ unsigned smem_u32(const void* p){
    return (unsigned)__cvta_generic_to_shared(p);
}
__device__ __forceinline__ float tf32r(float x){
    unsigned u;
    asm("cvt.rna.tf32.f32 %0, %1;\n" : "=r"(u) : "f"(x));
    return __uint_as_float(u);
}
__device__ __forceinline__ unsigned tf32b(float x){
    unsigned u;
    asm("cvt.rna.tf32.f32 %0, %1;\n" : "=r"(u) : "f"(x));
    return u;
}
__device__ __forceinline__ void mma_tf32(float c[4], const unsigned a[4], const unsigned b[2]){
    asm volatile("mma.sync.aligned.m16n8k8.row.col.f32.tf32.tf32.f32 "
        "{%0,%1,%2,%3}, {%4,%5,%6,%7}, {%8,%9}, {%0,%1,%2,%3};\n"
        : "+f"(c[0]),"+f"(c[1]),"+f"(c[2]),"+f"(c[3])
        : "r"(a[0]),"r"(a[1]),"r"(a[2]),"r"(a[3]), "r"(b[0]),"r"(b[1]));
}
__device__ __forceinline__ void cpa16(void* sdst, const void* gsrc){
    asm volatile("cp.async.cg.shared.global [%0], [%1], 16;\n"
        :: "r"(smem_u32(sdst)), "l"(gsrc));
}
__device__ __forceinline__ void cp_commit(){ asm volatile("cp.async.commit_group;\n"); }
template<int N> __device__ __forceinline__ void cp_wait(){
    asm volatile("cp.async.wait_group %0;\n" :: "n"(N));
}
__device__ __forceinline__ float sigmoidf_(float x){ return 1.f/(1.f+__expf(-x)); }
__device__ __forceinline__ unsigned U(const float* p){ return *(const unsigned*)p; }

// ---------------------------------------------------------------------------
// Prepack: fragment-order + tf32-round the 6 weight matrices
// A-pack idx: ((ct*16 + ks)*32 + lane); frag = rows (ct*16+g, +8), ks cols (tig, tig+4)
// B-pack idx: ((j8*16 + ks)*32 + lane); frag = out-chan (j8*8+g), ks cols (tig, tig+4)
// ---------------------------------------------------------------------------
__global__ void __launch_bounds__(256) prepack_kernel(
    const float* __restrict__ agw, const float* __restrict__ apw,
    const float* __restrict__ bgw, const float* __restrict__ bpw,
    const float* __restrict__ gw,  const float* __restrict__ zw)
{
    int tid = blockIdx.x*256 + threadIdx.x;
    if (tid < 5*4096) {
        int m = tid >> 12, idx = tid & 4095;
        const float* W = (m==0)?agw:(m==1)?apw:(m==2)?bgw:(m==3)?bpw:gw;
        int lane = idx & 31, ks = (idx>>5) & 15, ct = idx >> 9;
        int g = lane>>2, tig = lane&3;
        const float* base = W + (size_t)(ct*16+g)*CDIM + ks*8 + tig;
        uint4 v;
        v.x = tf32b(__ldg(base));
        v.y = tf32b(__ldg(base + 8*CDIM));
        v.z = tf32b(__ldg(base + 4));
        v.w = tf32b(__ldg(base + 8*CDIM + 4));
        g_wpA[tid] = v;
    } else if (tid < 5*4096 + 8192) {
        int idx = tid - 5*4096;
        int lane = idx & 31, ks = (idx>>5) & 15, j8 = idx >> 9;
        int g = lane>>2, tig = lane&3;
        const float* base = zw + (size_t)(j8*8+g)*CDIM + ks*8 + tig;
        g_wpB[idx] = make_uint2(tf32b(__ldg(base)), tf32b(__ldg(base + 4)));
    }
}

// ---------------------------------------------------------------------------
// Stage 1 (flipped GEMM, packed weights, gate fused into the two pair passes)
//   out[o][r] = W[o][:] . zn[r][:]; 64 rows/block; warp w covers channels w*16..+15
//   pass 0: a-pair + gate rows 0..31 ; pass 1: b-pair + gate rows 32..63
// ---------------------------------------------------------------------------
__global__ void __launch_bounds__(256,2) stage1_kernel(
    const float* __restrict__ z,   const float* __restrict__ mask,
    const float* __restrict__ lnw, const float* __restrict__ lnb,
    const float* __restrict__ agb, const float* __restrict__ apb,
    const float* __restrict__ bgb, const float* __restrict__ bpb,
    const float* __restrict__ gb)
{
    __shared__ float s_zn[64*136];
    __shared__ float s_msk[64];

    const int tid = threadIdx.x, lane = tid & 31, wid = tid >> 5;
    const int g = lane >> 2, tig = lane & 3;
    const int r0 = blockIdx.x * 64;

    if (tid < 64) s_msk[tid] = mask[r0 + tid];

    // LN: warp handles 8 rows; write tf32 zn, k-permuted within 8-groups, stride 136
    {
        float4 wv = *(const float4*)(lnw + lane*4);
        float4 bv = *(const float4*)(lnb + lane*4);
        for (int it = 0; it < 8; ++it) {
            int row = wid*8 + it;
            float4 v = *(const float4*)(z + (size_t)(r0+row)*CDIM + lane*4);
            float s = v.x+v.y+v.z+v.w;
            #pragma unroll
            for (int o=16;o;o>>=1) s += __shfl_xor_sync(0xffffffffu, s, o);
            float mu = s * (1.f/CDIM);
            float dx=v.x-mu, dy=v.y-mu, dz=v.z-mu, dw=v.w-mu;
            float vv = dx*dx+dy*dy+dz*dz+dw*dw;
            #pragma unroll
            for (int o=16;o;o>>=1) vv += __shfl_xor_sync(0xffffffffu, vv, o);
            float rs = rsqrtf(vv*(1.f/CDIM) + 1e-5f);
            float* dstp = s_zn + row*136 + (lane>>1)*8 + (lane&1);
            dstp[0] = tf32r(dx*rs*wv.x+bv.x);
            dstp[2] = tf32r(dy*rs*wv.y+bv.y);
            dstp[4] = tf32r(dz*rs*wv.z+bv.z);
            dstp[6] = tf32r(dw*rs*wv.w+bv.w);
        }
    }
    __syncthreads();

    const int m0 = wid*16;
    const uint4* wbase = g_wpA + wid*512 + lane;
    const float  bs0 = __ldg(gb+m0+g), bs8 = __ldg(gb+m0+g+8);

    #pragma unroll
    for (int ps = 0; ps < 2; ++ps) {
        const uint4* pG = wbase + (ps ? 2*4096 : 0);
        const uint4* pP = wbase + (ps ? 3*4096 : 1*4096);
        const uint4* pS = wbase + 4*4096;
        const float* b1v = ps ? bgb : agb;
        const float* b2v = ps ? bpb : apb;
        float* dst = ps ? g_bufB : g_bufA;
        const int glo = ps*4;                  // gate row-tiles this pass

        float accG[8][4], accP[8][4], accS[4][4];
        #pragma unroll
        for (int i=0;i<8;++i){
            #pragma unroll
            for (int j=0;j<4;++j){ accG[i][j]=0.f; accP[i][j]=0.f; }
        }
        #pragma unroll
        for (int i=0;i<4;++i){
            #pragma unroll
            for (int j=0;j<4;++j) accS[i][j]=0.f;
        }

        #pragma unroll 2
        for (int ks=0; ks<16; ++ks) {
            uint4 a1 = __ldg(pG + ks*32);
            uint4 a2 = __ldg(pP + ks*32);
            uint4 a3 = __ldg(pS + ks*32);
            #pragma unroll
            for (int nt=0; nt<8; ++nt) {
                float2 bb = *(const float2*)(s_zn + (nt*8+g)*136 + ks*8 + 2*tig);
                unsigned b[2] = { U(&bb.x), U(&bb.y) };
                mma_tf32(accG[nt], (const unsigned*)&a1, b);
                mma_tf32(accP[nt], (const unsigned*)&a2, b);
                if (nt >= glo && nt < glo+4)
                    mma_tf32(accS[nt-glo], (const unsigned*)&a3, b);
            }
        }

        // pair epilogue: tf32( mask * sigmoid(G+b1) * (P+b2) ), d-major
        const float bG0 = __ldg(b1v+m0+g), bG8 = __ldg(b1v+m0+g+8);
        const float bP0 = __ldg(b2v+m0+g), bP8 = __ldg(b2v+m0+g+8);
        #pragma unroll
        for (int nt=0; nt<8; ++nt) {
            const int rr = nt*8 + tig*2;
            const float mk0 = s_msk[rr], mk1 = s_msk[rr+1];
            float2 o0, o1;
            o0.x = tf32r(mk0 * sigmoidf_(accG[nt][0]+bG0) * (accP[nt][0]+bP0));
            o0.y = tf32r(mk1 * sigmoidf_(accG[nt][1]+bG0) * (accP[nt][1]+bP0));
            o1.x = tf32r(mk0 * sigmoidf_(accG[nt][2]+bG8) * (accP[nt][2]+bP8));
            o1.y = tf32r(mk1 * sigmoidf_(accG[nt][3]+bG8) * (accP[nt][3]+bP8));
            *(float2*)(dst + (size_t)(m0+g)*NN   + r0 + rr) = o0;
            *(float2*)(dst + (size_t)(m0+g+8)*NN + r0 + rr) = o1;
        }
        // gate epilogue (rows glo*8 .. glo*8+31)
        #pragma unroll
        for (int nt2=0; nt2<4; ++nt2) {
            const int rr = (glo+nt2)*8 + tig*2;
            float2 o0, o1;
            o0.x = sigmoidf_(accS[nt2][0]+bs0);
            o0.y = sigmoidf_(accS[nt2][1]+bs0);
            o1.x = sigmoidf_(accS[nt2][2]+bs8);
            o1.y = sigmoidf_(accS[nt2][3]+bs8);
            *(float2*)(g_bufG + (size_t)(m0+g)*NN   + r0 + rr) = o0;
            *(float2*)(g_bufG + (size_t)(m0+g+8)*NN + r0 + rr) = o1;
        }
    }
}

// ---------------------------------------------------------------------------
// Stage 2: per-d tf32 GEMM x[d] = a[d] @ b[d]. 128x128 tile, kt=32, cp.async 2-buf
// ---------------------------------------------------------------------------
__global__ void __launch_bounds__(256) stage2_kernel()
{
    extern __shared__ char smraw[];
    float* As = (float*)smraw;            // [2][128*36]  [i][k]
    float* Bs = As + 2*128*36;            // [2][32*132]  [k][j]

    const int d = blockIdx.z;
    const float* gA = g_bufA + (size_t)d*NN;
    const float* gB = g_bufB + (size_t)d*NN;
    float* gC = g_bufX + (size_t)d*NN;
    const int i0 = blockIdx.y*128, j0 = blockIdx.x*128;
    const int tid = threadIdx.x, lane = tid&31, wid = tid>>5;
    const int g = lane >> 2, tig = lane & 3;
    const int wm = wid & 3, wn = wid >> 2;    // warp tile 32(m) x 64(n)

    float acc[2][8][4];
    #pragma unroll
    for (int a=0;a<2;++a){
        #pragma unroll
        for(int b=0;b<8;++b){
            #pragma unroll
            for(int c=0;c<4;++c) acc[a][b][c]=0.f;
        }
    }

    auto load_tile = [&](int kt, int buf){
        float* Ab = As + buf*128*36;
        float* Bb = Bs + buf*32*132;
        #pragma unroll
        for (int i=0;i<4;++i){
            int cid = tid + i*256;
            int r = cid>>3, kc = (cid&7)*4;
            cpa16(Ab + r*36 + kc, gA + (size_t)(i0+r)*NSEQ + kt + kc);
        }
        #pragma unroll
        for (int i=0;i<4;++i){
            int cid = tid + i*256;
            int kk = cid>>5, jc = (cid&31)*4;
            cpa16(Bb + kk*132 + jc, gB + (size_t)(kt+kk)*NSEQ + j0 + jc);
        }
        cp_commit();
    };

    load_tile(0, 0);
    int buf = 0;
    for (int t=0; t<16; ++t) {
        if (t < 15) { load_tile((t+1)*32, buf^1); cp_wait<1>(); }
        else        { cp_wait<0>(); }
        __syncthreads();
        const float* Ab = As + buf*128*36;
        const float* Bb = Bs + buf*32*132;
        #pragma unroll
        for (int ks=0; ks<4; ++ks) {
            unsigned a[2][4];
            #pragma unroll
            for (int mt=0; mt<2; ++mt) {
                const float* ap = Ab + (wm*32 + mt*16 + g)*36 + ks*8 + tig;
                a[mt][0]=U(ap); a[mt][1]=U(ap + 8*36); a[mt][2]=U(ap + 4); a[mt][3]=U(ap + 8*36 + 4);
            }
            #pragma unroll
            for (int nt=0; nt<8; ++nt) {
                const float* bp = Bb + (ks*8 + tig)*132 + wn*64 + nt*8 + g;
                unsigned b[2] = { U(bp), U(bp + 4*132) };
                mma_tf32(acc[0][nt], a[0], b);
                mma_tf32(acc[1][nt], a[1], b);
            }
        }
        __syncthreads();
        buf ^= 1;
    }

    #pragma unroll
    for (int mt=0; mt<2; ++mt){
        #pragma unroll
        for (int nt=0; nt<8; ++nt) {
            int r = i0 + wm*32 + mt*16 + g;
            int c = j0 + wn*64 + nt*8 + tig*2;
            *(float2*)(gC + (size_t)r*NSEQ + c)     = make_float2(acc[mt][nt][0], acc[mt][nt][1]);
            *(float2*)(gC + (size_t)(r+8)*NSEQ + c) = make_float2(acc[mt][nt][2], acc[mt][nt][3]);
        }
    }
}

// ---------------------------------------------------------------------------
// Stage 3: gather x, LN -> tf32 (k-permuted smem), final projection with
// packed B-fragment weights, gate multiply, store. 64 rows/block.
// Warp w: rows m0=(w&3)*16, output cols n0=(w>>2)*64.
// ---------------------------------------------------------------------------
__global__ void __launch_bounds__(256,2) stage3_kernel(
    const float* __restrict__ lnow, const float* __restrict__ lnob,
    const float* __restrict__ zb,   float* __restrict__ out)
{
    extern __shared__ char smraw[];
    float* s_x  = (float*)smraw;          // [64][133]  x, then gate, [r][d]
    float* s_xn = s_x + 64*133;           // [64][136]  tf32, k-permuted

    const int tid = threadIdx.x, lane = tid&31, wid = tid>>5;
    const int g = lane >> 2, tig = lane & 3;
    const int bi = blockIdx.x;
    const int ti = bi >> 3, j0 = (bi & 7)*64;
    const size_t rbase = (size_t)ti*NSEQ + j0;

    // gather x[d][rbase + rc] -> s_x[r][d]
    #pragma unroll
    for (int it=0; it<8; ++it){
        int cid = tid + it*256; int dd = cid>>4; int rc = (cid&15)*4;
        float4 v = *(const float4*)(g_bufX + (size_t)dd*NN + rbase + rc);
        s_x[(rc+0)*133 + dd] = v.x;
        s_x[(rc+1)*133 + dd] = v.y;
        s_x[(rc+2)*133 + dd] = v.z;
        s_x[(rc+3)*133 + dd] = v.w;
    }
    __syncthreads();

    // LN over d -> tf32, k-permuted, stride 136
    {
        float4 wv = *(const float4*)(lnow + lane*4);
        float4 bv = *(const float4*)(lnob + lane*4);
        for (int it=0; it<8; ++it){
            int row = wid*8 + it;
            const float* rp = s_x + row*133 + lane*4;
            float e0=rp[0], e1=rp[1], e2=rp[2], e3=rp[3];
            float s = e0+e1+e2+e3;
            #pragma unroll
            for (int o=16;o;o>>=1) s += __shfl_xor_sync(0xffffffffu, s, o);
            float mu = s*(1.f/CDIM);
            float dx=e0-mu, dy=e1-mu, dz=e2-mu, dw=e3-mu;
            float vv = dx*dx+dy*dy+dz*dz+dw*dw;
            #pragma unroll
            for (int o=16;o;o>>=1) vv += __shfl_xor_sync(0xffffffffu, vv, o);
            float rs = rsqrtf(vv*(1.f/CDIM)+1e-5f);
            float* dp = s_xn + row*136 + (lane>>1)*8 + (lane&1);
            dp[0] = tf32r(dx*rs*wv.x+bv.x);
            dp[2] = tf32r(dy*rs*wv.y+bv.y);
            dp[4] = tf32r(dz*rs*wv.z+bv.z);
            dp[6] = tf32r(dw*rs*wv.w+bv.w);
        }
    }
    __syncthreads();

    // gate gather overwrites s_x
    #pragma unroll
    for (int it=0; it<8; ++it){
        int cid = tid + it*256; int dd = cid>>4; int rc = (cid&15)*4;
        float4 v = *(const float4*)(g_bufG + (size_t)dd*NN + rbase + rc);
        s_x[(rc+0)*133 + dd] = v.x;
        s_x[(rc+1)*133 + dd] = v.y;
        s_x[(rc+2)*133 + dd] = v.z;
        s_x[(rc+3)*133 + dd] = v.w;
    }
    __syncthreads();

    const int m0 = (wid&3)*16, n0 = (wid>>2)*64;
    float acc[8][4];
    #pragma unroll
    for (int i=0;i<8;++i){
        #pragma unroll
        for(int j=0;j<4;++j) acc[i][j]=0.f;
    }
    #pragma unroll 4
    for (int ks=0; ks<16; ++ks) {
        unsigned a[4];
        float2 p0 = *(const float2*)(s_xn + (m0+g)*136   + ks*8 + 2*tig);
        float2 p1 = *(const float2*)(s_xn + (m0+g+8)*136 + ks*8 + 2*tig);
        a[0]=U(&p0.x); a[1]=U(&p1.x); a[2]=U(&p0.y); a[3]=U(&p1.y);
        #pragma unroll
        for (int nt=0; nt<8; ++nt) {
            uint2 bw = __ldg(g_wpB + ((n0>>3)+nt)*512 + ks*32 + lane);
            unsigned b[2] = { bw.x, bw.y };
            mma_tf32(acc[nt], a, b);
        }
    }

    #pragma unroll
    for (int nt=0; nt<8; ++nt){
        const int o = n0 + nt*8 + tig*2;
        const float zb0 = __ldg(zb+o), zb1 = __ldg(zb+o+1);
        {
            int r = m0 + g;
            float2 ov = make_float2((acc[nt][0]+zb0) * s_x[r*133+o],
                                    (acc[nt][1]+zb1) * s_x[r*133+o+1]);
            *(float2*)(out + (rbase + r)*CDIM + o) = ov;
        }
        {
            int r = m0 + g + 8;
            float2 ov = make_float2((acc[nt][2]+zb0) * s_x[r*133+o],
                                    (acc[nt][3]+zb1) * s_x[r*133+o+1]);
            *(float2*)(out + (rbase + r)*CDIM + o) = ov;
        }
    }
}

// ---------------------------------------------------------------------------
extern "C" void kernel_launch(void* const* d_in, const int* in_sizes, int n_in,
                              void* d_out, int out_size)
{
    const float* z    = (const float*)d_in[0];
    const float* mask = (const float*)d_in[1];
    const float* lniw = (const float*)d_in[2];
    const float* lnib = (const float*)d_in[3];
    const float* agw  = (const float*)d_in[4];
    const float* agb  = (const float*)d_in[5];
    const float* apw  = (const float*)d_in[6];
    const float* apb  = (const float*)d_in[7];
    const float* bgw  = (const float*)d_in[8];
    const float* bgb  = (const float*)d_in[9];
    const float* bpw  = (const float*)d_in[10];
    const float* bpb  = (const float*)d_in[11];
    const float* lnow = (const float*)d_in[12];
    const float* lnob = (const float*)d_in[13];
    const float* zw   = (const float*)d_in[14];
    const float* zb   = (const float*)d_in[15];
    const float* gww  = (const float*)d_in[16];
    const float* gwb  = (const float*)d_in[17];
    float* out = (float*)d_out;

    const int SMEM2 = (2*128*36 + 2*32*132) * 4;   // ~69 KB
    const int SMEM3 = (64*133 + 64*136) * 4;       // ~69 KB
    cudaFuncSetAttribute(stage2_kernel, cudaFuncAttributeMaxDynamicSharedMemorySize, SMEM2);
    cudaFuncSetAttribute(stage3_kernel, cudaFuncAttributeMaxDynamicSharedMemorySize, SMEM3);

    prepack_kernel<<<113, 256>>>(agw, apw, bgw, bpw, gww, zw);
    stage1_kernel<<<NN/64, 256>>>(z, mask, lniw, lnib,
                                  agb, apb, bgb, bpb, gwb);
    stage2_kernel<<<dim3(4,4,128), 256, SMEM2>>>();
    stage3_kernel<<<NN/64, 256, SMEM3>>>(lnow, lnob, zb, out);
}

// round 8
// speedup vs baseline: 6.1028x; 1.4356x over previous
#include <cuda_runtime.h>
#include <cuda_fp16.h>
#include <cstdint>

#define NSEQ 512
#define CDIM 128
#define NN (NSEQ*NSEQ)

// scratch
__device__ __half g_bufA[(size_t)CDIM*NN];  // a[i,k,d] -> [d][i*512+k]  fp16
__device__ __half g_bufB[(size_t)CDIM*NN];  // b[k,j,d] -> [d][k*512+j]  fp16
__device__ float  g_bufG[(size_t)CDIM*NN];  // gate     -> [d][i*512+j]  fp32
__device__ float  g_bufX[(size_t)CDIM*NN];  // x        -> [d][i*512+j]  fp32

// prepacked fp16 weights, m16n8k16 fragment order
// A-pack (stage1): [m][ct][ks][lane] uint4 ; m: 0=agw 1=apw 2=bgw 3=bpw 4=gw
__device__ uint4 g_wpA[5*2048];
// B-pack (stage3, zw): [j8][ks][lane] uint2
__device__ uint2 g_wpB[4096];

// ---------------------------------------------------------------- helpers
__device__ __forceinline__ unsigned smem_u32(const void* p){
    return (unsigned)__cvta_generic_to_shared(p);
}
__device__ __forceinline__ unsigned h2u(float a, float b){
    __half2 h = __floats2half2_rn(a, b);
    return *(unsigned*)&h;
}
__device__ __forceinline__ void mma_f16(float c[4], const unsigned a[4], const unsigned b[2]){
    asm volatile("mma.sync.aligned.m16n8k16.row.col.f32.f16.f16.f32 "
        "{%0,%1,%2,%3}, {%4,%5,%6,%7}, {%8,%9}, {%0,%1,%2,%3};\n"
        : "+f"(c[0]),"+f"(c[1]),"+f"(c[2]),"+f"(c[3])
        : "r"(a[0]),"r"(a[1]),"r"(a[2]),"r"(a[3]), "r"(b[0]),"r"(b[1]));
}
__device__ __forceinline__ void ldmx4(unsigned r[4], unsigned addr){
    asm volatile("ldmatrix.sync.aligned.m8n8.x4.shared.b16 {%0,%1,%2,%3}, [%4];\n"
        : "=r"(r[0]),"=r"(r[1]),"=r"(r[2]),"=r"(r[3]) : "r"(addr));
}
__device__ __forceinline__ void ldmx2t(unsigned r[2], unsigned addr){
    asm volatile("ldmatrix.sync.aligned.m8n8.x2.trans.shared.b16 {%0,%1}, [%2];\n"
        : "=r"(r[0]),"=r"(r[1]) : "r"(addr));
}
__device__ __forceinline__ void cpa16(void* sdst, const void* gsrc){
    asm volatile("cp.async.cg.shared.global [%0], [%1], 16;\n"
        :: "r"(smem_u32(sdst)), "l"(gsrc));
}
__device__ __forceinline__ void cp_commit(){ asm volatile("cp.async.commit_group;\n"); }
template<int N> __device__ __forceinline__ void cp_wait(){
    asm volatile("cp.async.wait_group %0;\n" :: "n"(N));
}
__device__ __forceinline__ float sigmoidf_(float x){ return 1.f/(1.f+__expf(-x)); }
__device__ __forceinline__ unsigned US(const __half* p){ return *(const unsigned*)p; }

#define ZSTRIDE 136   // halves per smem row (128 data + 8 pad)

// ---------------------------------------------------------------------------
// Prepack: fp16 fragment-order weights (m16n8k16)
// ---------------------------------------------------------------------------
__global__ void __launch_bounds__(256) prepack_kernel(
    const float* __restrict__ agw, const float* __restrict__ apw,
    const float* __restrict__ bgw, const float* __restrict__ bpw,
    const float* __restrict__ gw,  const float* __restrict__ zw)
{
    int tid = blockIdx.x*256 + threadIdx.x;
    if (tid < 5*2048) {
        int m = tid >> 11, idx = tid & 2047;
        const float* W = (m==0)?agw:(m==1)?apw:(m==2)?bgw:(m==3)?bpw:gw;
        int lane = idx & 31, ks = (idx>>5) & 7, ct = idx >> 8;
        int g = lane>>2, tig = lane&3;
        const float* r0p = W + (size_t)(ct*16+g)*CDIM + ks*16 + tig*2;
        const float* r8p = r0p + 8*CDIM;
        uint4 v;
        v.x = h2u(r0p[0], r0p[1]);
        v.y = h2u(r8p[0], r8p[1]);
        v.z = h2u(r0p[8], r0p[9]);
        v.w = h2u(r8p[8], r8p[9]);
        g_wpA[tid] = v;
    } else if (tid < 5*2048 + 4096) {
        int idx = tid - 5*2048;
        int lane = idx & 31, ks = (idx>>5) & 7, j8 = idx >> 8;
        int g = lane>>2, tig = lane&3;
        const float* bp = zw + (size_t)(j8*8+g)*CDIM + ks*16 + tig*2;
        g_wpB[idx] = make_uint2(h2u(bp[0], bp[1]), h2u(bp[8], bp[9]));
    }
}

// ---------------------------------------------------------------------------
// Stage 1 (flipped GEMM, fp16): out[o][r] = W[o][:] . zn[r][:]
// 64 rows/block; warp w covers channels w*16..+15; gate split across 2 passes.
// ---------------------------------------------------------------------------
__global__ void __launch_bounds__(256,2) stage1_kernel(
    const float* __restrict__ z,   const float* __restrict__ mask,
    const float* __restrict__ lnw, const float* __restrict__ lnb,
    const float* __restrict__ agb, const float* __restrict__ apb,
    const float* __restrict__ bgb, const float* __restrict__ bpb,
    const float* __restrict__ gb)
{
    __shared__ __half s_zn[64*ZSTRIDE];   // [r][c]
    __shared__ float  s_msk[64];

    const int tid = threadIdx.x, lane = tid & 31, wid = tid >> 5;
    const int g = lane >> 2, tig = lane & 3;
    const int r0 = blockIdx.x * 64;

    if (tid < 64) s_msk[tid] = mask[r0 + tid];

    // LN: warp handles 8 rows; write fp16 zn
    {
        float4 wv = *(const float4*)(lnw + lane*4);
        float4 bv = *(const float4*)(lnb + lane*4);
        for (int it = 0; it < 8; ++it) {
            int row = wid*8 + it;
            float4 v = *(const float4*)(z + (size_t)(r0+row)*CDIM + lane*4);
            float s = v.x+v.y+v.z+v.w;
            #pragma unroll
            for (int o=16;o;o>>=1) s += __shfl_xor_sync(0xffffffffu, s, o);
            float mu = s * (1.f/CDIM);
            float dx=v.x-mu, dy=v.y-mu, dz=v.z-mu, dw=v.w-mu;
            float vv = dx*dx+dy*dy+dz*dz+dw*dw;
            #pragma unroll
            for (int o=16;o;o>>=1) vv += __shfl_xor_sync(0xffffffffu, vv, o);
            float rs = rsqrtf(vv*(1.f/CDIM) + 1e-5f);
            __half* dp = s_zn + row*ZSTRIDE + lane*4;
            *(unsigned*)(dp)     = h2u(dx*rs*wv.x+bv.x, dy*rs*wv.y+bv.y);
            *(unsigned*)(dp + 2) = h2u(dz*rs*wv.z+bv.z, dw*rs*wv.w+bv.w);
        }
    }
    __syncthreads();

    const int m0 = wid*16;
    const uint4* wbase = g_wpA + wid*256 + lane;   // [m][ct=wid][ks][lane]
    const float  bs0 = __ldg(gb+m0+g), bs8 = __ldg(gb+m0+g+8);

    #pragma unroll
    for (int ps = 0; ps < 2; ++ps) {
        const uint4* pG = wbase + (ps ? 2*2048 : 0);
        const uint4* pP = wbase + (ps ? 3*2048 : 1*2048);
        const uint4* pS = wbase + 4*2048;
        const float* b1v = ps ? bgb : agb;
        const float* b2v = ps ? bpb : apb;
        __half* dst = ps ? g_bufB : g_bufA;
        const int glo = ps*4;

        float accG[8][4], accP[8][4], accS[4][4];
        #pragma unroll
        for (int i=0;i<8;++i){
            #pragma unroll
            for (int j=0;j<4;++j){ accG[i][j]=0.f; accP[i][j]=0.f; }
        }
        #pragma unroll
        for (int i=0;i<4;++i){
            #pragma unroll
            for (int j=0;j<4;++j) accS[i][j]=0.f;
        }

        #pragma unroll 2
        for (int ks=0; ks<8; ++ks) {
            uint4 a1 = __ldg(pG + ks*32);
            uint4 a2 = __ldg(pP + ks*32);
            uint4 a3 = __ldg(pS + ks*32);
            #pragma unroll
            for (int nt=0; nt<8; ++nt) {
                const __half* bp = s_zn + (nt*8+g)*ZSTRIDE + ks*16 + 2*tig;
                unsigned b[2] = { US(bp), US(bp + 8) };
                mma_f16(accG[nt], (const unsigned*)&a1, b);
                mma_f16(accP[nt], (const unsigned*)&a2, b);
                if (nt >= glo && nt < glo+4)
                    mma_f16(accS[nt-glo], (const unsigned*)&a3, b);
            }
        }

        // pair epilogue: fp16( mask * sigmoid(G+b1) * (P+b2) ), d-major
        const float bG0 = __ldg(b1v+m0+g), bG8 = __ldg(b1v+m0+g+8);
        const float bP0 = __ldg(b2v+m0+g), bP8 = __ldg(b2v+m0+g+8);
        #pragma unroll
        for (int nt=0; nt<8; ++nt) {
            const int rr = nt*8 + tig*2;
            const float mk0 = s_msk[rr], mk1 = s_msk[rr+1];
            unsigned o0 = h2u(mk0 * sigmoidf_(accG[nt][0]+bG0) * (accP[nt][0]+bP0),
                              mk1 * sigmoidf_(accG[nt][1]+bG0) * (accP[nt][1]+bP0));
            unsigned o1 = h2u(mk0 * sigmoidf_(accG[nt][2]+bG8) * (accP[nt][2]+bP8),
                              mk1 * sigmoidf_(accG[nt][3]+bG8) * (accP[nt][3]+bP8));
            *(unsigned*)(dst + (size_t)(m0+g)*NN   + r0 + rr) = o0;
            *(unsigned*)(dst + (size_t)(m0+g+8)*NN + r0 + rr) = o1;
        }
        // gate epilogue (fp32), rows glo*8 .. glo*8+31
        #pragma unroll
        for (int nt2=0; nt2<4; ++nt2) {
            const int rr = (glo+nt2)*8 + tig*2;
            float2 o0, o1;
            o0.x = sigmoidf_(accS[nt2][0]+bs0);
            o0.y = sigmoidf_(accS[nt2][1]+bs0);
            o1.x = sigmoidf_(accS[nt2][2]+bs8);
            o1.y = sigmoidf_(accS[nt2][3]+bs8);
            *(float2*)(g_bufG + (size_t)(m0+g)*NN   + r0 + rr) = o0;
            *(float2*)(g_bufG + (size_t)(m0+g+8)*NN + r0 + rr) = o1;
        }
    }
}

// ---------------------------------------------------------------------------
// Stage 2: per-d fp16 GEMM x[d] = a[d] @ b[d], fp32 out. 128x128 tile,
// kt=32, cp.async 2-buf, ldmatrix(+trans). (structure validated in round 2)
// ---------------------------------------------------------------------------
__global__ void __launch_bounds__(256,2) stage2_kernel()
{
    __shared__ __align__(16) __half As[2][128*40];   // [i][k], pad 40
    __shared__ __align__(16) __half Bs[2][32*136];   // [k][j], pad 136

    const int d = blockIdx.z;
    const __half* gA = g_bufA + (size_t)d*NN;
    const __half* gB = g_bufB + (size_t)d*NN;
    float* gC = g_bufX + (size_t)d*NN;
    const int i0 = blockIdx.y*128, j0 = blockIdx.x*128;
    const int tid = threadIdx.x, lane = tid&31, wid = tid>>5;
    const int wm = wid & 3, wn = wid >> 2;    // 4x2 warp grid: 32 rows x 64 cols

    float acc[2][8][4];
    #pragma unroll
    for (int a=0;a<2;++a){
        #pragma unroll
        for(int b=0;b<8;++b){
            #pragma unroll
            for(int c=0;c<4;++c) acc[a][b][c]=0.f;
        }
    }

    auto load_tile = [&](int kt, int buf){
        #pragma unroll
        for (int i=0;i<2;++i){
            int cid = tid + i*256;
            int r = cid>>2, kc = (cid&3)*8;
            cpa16(&As[buf][r*40+kc], gA + (size_t)(i0+r)*NSEQ + kt + kc);
        }
        #pragma unroll
        for (int i=0;i<2;++i){
            int cid = tid + i*256;
            int kk = cid>>4, jc = (cid&15)*8;
            cpa16(&Bs[buf][kk*136+jc], gB + (size_t)(kt+kk)*NSEQ + j0 + jc);
        }
        cp_commit();
    };

    load_tile(0, 0);
    int buf = 0;
    for (int t=0; t<16; ++t) {
        if (t < 15) { load_tile((t+1)*32, buf^1); cp_wait<1>(); }
        else        { cp_wait<0>(); }
        __syncthreads();
        #pragma unroll
        for (int ks=0; ks<2; ++ks) {
            unsigned afr[2][4];
            #pragma unroll
            for (int mt=0; mt<2; ++mt)
                ldmx4(afr[mt], smem_u32(&As[buf][(wm*32 + mt*16 + (lane&15))*40
                                                 + ks*16 + (lane>>4)*8]));
            #pragma unroll
            for (int nt=0; nt<8; ++nt) {
                unsigned b[2];
                ldmx2t(b, smem_u32(&Bs[buf][(ks*16 + (lane&15))*136 + wn*64 + nt*8]));
                mma_f16(acc[0][nt], afr[0], b);
                mma_f16(acc[1][nt], afr[1], b);
            }
        }
        __syncthreads();
        buf ^= 1;
    }

    #pragma unroll
    for (int mt=0; mt<2; ++mt){
        #pragma unroll
        for (int nt=0; nt<8; ++nt) {
            int r = i0 + wm*32 + mt*16 + (lane>>2);
            int c = j0 + wn*64 + nt*8 + (lane&3)*2;
            *(float2*)(gC + (size_t)r*NSEQ + c)     = make_float2(acc[mt][nt][0], acc[mt][nt][1]);
            *(float2*)(gC + (size_t)(r+8)*NSEQ + c) = make_float2(acc[mt][nt][2], acc[mt][nt][3]);
        }
    }
}

// ---------------------------------------------------------------------------
// Stage 3: gather x, LN -> fp16, final projection (packed zw), gate, store.
// 64 rows/block; warp w: rows m0=(w&3)*16, output cols n0=(w>>2)*64.
// ---------------------------------------------------------------------------
__global__ void __launch_bounds__(256,2) stage3_kernel(
    const float* __restrict__ lnow, const float* __restrict__ lnob,
    const float* __restrict__ zb,   float* __restrict__ out)
{
    extern __shared__ char smraw[];
    float*  s_x  = (float*)smraw;                 // [64][133]  x, then gate
    __half* s_xn = (__half*)(s_x + 64*133);       // [64][ZSTRIDE] fp16

    const int tid = threadIdx.x, lane = tid&31, wid = tid>>5;
    const int g = lane >> 2, tig = lane & 3;
    const int bi = blockIdx.x;
    const int ti = bi >> 3, j0 = (bi & 7)*64;
    const size_t rbase = (size_t)ti*NSEQ + j0;

    // gather x[d][rbase + rc] -> s_x[r][d]
    #pragma unroll
    for (int it=0; it<8; ++it){
        int cid = tid + it*256; int dd = cid>>4; int rc = (cid&15)*4;
        float4 v = *(const float4*)(g_bufX + (size_t)dd*NN + rbase + rc);
        s_x[(rc+0)*133 + dd] = v.x;
        s_x[(rc+1)*133 + dd] = v.y;
        s_x[(rc+2)*133 + dd] = v.z;
        s_x[(rc+3)*133 + dd] = v.w;
    }
    __syncthreads();

    // LN over d -> fp16
    {
        float4 wv = *(const float4*)(lnow + lane*4);
        float4 bv = *(const float4*)(lnob + lane*4);
        for (int it=0; it<8; ++it){
            int row = wid*8 + it;
            const float* rp = s_x + row*133 + lane*4;
            float e0=rp[0], e1=rp[1], e2=rp[2], e3=rp[3];
            float s = e0+e1+e2+e3;
            #pragma unroll
            for (int o=16;o;o>>=1) s += __shfl_xor_sync(0xffffffffu, s, o);
            float mu = s*(1.f/CDIM);
            float dx=e0-mu, dy=e1-mu, dz=e2-mu, dw=e3-mu;
            float vv = dx*dx+dy*dy+dz*dz+dw*dw;
            #pragma unroll
            for (int o=16;o;o>>=1) vv += __shfl_xor_sync(0xffffffffu, vv, o);
            float rs = rsqrtf(vv*(1.f/CDIM)+1e-5f);
            __half* dp = s_xn + row*ZSTRIDE + lane*4;
            *(unsigned*)(dp)     = h2u(dx*rs*wv.x+bv.x, dy*rs*wv.y+bv.y);
            *(unsigned*)(dp + 2) = h2u(dz*rs*wv.z+bv.z, dw*rs*wv.w+bv.w);
        }
    }
    __syncthreads();

    // gate gather overwrites s_x
    #pragma unroll
    for (int it=0; it<8; ++it){
        int cid = tid + it*256; int dd = cid>>4; int rc = (cid&15)*4;
        float4 v = *(const float4*)(g_bufG + (size_t)dd*NN + rbase + rc);
        s_x[(rc+0)*133 + dd] = v.x;
        s_x[(rc+1)*133 + dd] = v.y;
        s_x[(rc+2)*133 + dd] = v.z;
        s_x[(rc+3)*133 + dd] = v.w;
    }
    __syncthreads();

    const int m0 = (wid&3)*16, n0 = (wid>>2)*64;
    float acc[8][4];
    #pragma unroll
    for (int i=0;i<8;++i){
        #pragma unroll
        for(int j=0;j<4;++j) acc[i][j]=0.f;
    }
    #pragma unroll 2
    for (int ks=0; ks<8; ++ks) {
        unsigned a[4];
        const __half* p0 = s_xn + (m0+g)*ZSTRIDE   + ks*16 + 2*tig;
        const __half* p1 = s_xn + (m0+g+8)*ZSTRIDE + ks*16 + 2*tig;
        a[0]=US(p0); a[1]=US(p1); a[2]=US(p0+8); a[3]=US(p1+8);
        #pragma unroll
        for (int nt=0; nt<8; ++nt) {
            uint2 bw = __ldg(g_wpB + ((n0>>3)+nt)*256 + ks*32 + lane);
            unsigned b[2] = { bw.x, bw.y };
            mma_f16(acc[nt], a, b);
        }
    }

    #pragma unroll
    for (int nt=0; nt<8; ++nt){
        const int o = n0 + nt*8 + tig*2;
        const float zb0 = __ldg(zb+o), zb1 = __ldg(zb+o+1);
        {
            int r = m0 + g;
            float2 ov = make_float2((acc[nt][0]+zb0) * s_x[r*133+o],
                                    (acc[nt][1]+zb1) * s_x[r*133+o+1]);
            *(float2*)(out + (rbase + r)*CDIM + o) = ov;
        }
        {
            int r = m0 + g + 8;
            float2 ov = make_float2((acc[nt][2]+zb0) * s_x[r*133+o],
                                    (acc[nt][3]+zb1) * s_x[r*133+o+1]);
            *(float2*)(out + (rbase + r)*CDIM + o) = ov;
        }
    }
}

// ---------------------------------------------------------------------------
extern "C" void kernel_launch(void* const* d_in, const int* in_sizes, int n_in,
                              void* d_out, int out_size)
{
    const float* z    = (const float*)d_in[0];
    const float* mask = (const float*)d_in[1];
    const float* lniw = (const float*)d_in[2];
    const float* lnib = (const float*)d_in[3];
    const float* agw  = (const float*)d_in[4];
    const float* agb  = (const float*)d_in[5];
    const float* apw  = (const float*)d_in[6];
    const float* apb  = (const float*)d_in[7];
    const float* bgw  = (const float*)d_in[8];
    const float* bgb  = (const float*)d_in[9];
    const float* bpw  = (const float*)d_in[10];
    const float* bpb  = (const float*)d_in[11];
    const float* lnow = (const float*)d_in[12];
    const float* lnob = (const float*)d_in[13];
    const float* zw   = (const float*)d_in[14];
    const float* zb   = (const float*)d_in[15];
    const float* gww  = (const float*)d_in[16];
    const float* gwb  = (const float*)d_in[17];
    float* out = (float*)d_out;

    const int SMEM3 = 64*133*4 + 64*ZSTRIDE*2;     // ~51 KB
    cudaFuncSetAttribute(stage3_kernel, cudaFuncAttributeMaxDynamicSharedMemorySize, SMEM3);

    prepack_kernel<<<56, 256>>>(agw, apw, bgw, bpw, gww, zw);
    stage1_kernel<<<NN/64, 256>>>(z, mask, lniw, lnib,
                                  agb, apb, bgb, bpb, gwb);
    stage2_kernel<<<dim3(4,4,128), 256>>>();
    stage3_kernel<<<NN/64, 256, SMEM3>>>(lnow, lnob, zb, out);
}

// round 11
// speedup vs baseline: 6.2236x; 1.0198x over previous
#include <cuda_runtime.h>
#include <cuda_fp16.h>
#include <cstdint>

#define NSEQ 512
#define CDIM 128
#define NN (NSEQ*NSEQ)

// scratch (all fp16 now)
__device__ __half g_bufA[(size_t)CDIM*NN];  // a[i,k,d] -> [d][i*512+k]
__device__ __half g_bufB[(size_t)CDIM*NN];  // b[k,j,d] -> [d][k*512+j]
__device__ __half g_bufG[(size_t)CDIM*NN];  // gate     -> [d][i*512+j]
__device__ __half g_bufX[(size_t)CDIM*NN];  // x        -> [d][i*512+j]

// prepacked fp16 weights, m16n8k16 fragment order
// A-pack (stage1): [m][ct][ks][lane] uint4 ; m: 0=agw 1=apw 2=bgw 3=bpw 4=gw
__device__ uint4 g_wpA[5*2048];
// B-pack (stage3, zw): [j8][ks][lane] uint2
__device__ uint2 g_wpB[4096];

// ---------------------------------------------------------------- helpers
__device__ __forceinline__ unsigned smem_u32(const void* p){
    return (unsigned)__cvta_generic_to_shared(p);
}
__device__ __forceinline__ unsigned h2u(float a, float b){
    __half2 h = __floats2half2_rn(a, b);
    return *(unsigned*)&h;
}
__device__ __forceinline__ void mma_f16(float c[4], const unsigned a[4], const unsigned b[2]){
    asm volatile("mma.sync.aligned.m16n8k16.row.col.f32.f16.f16.f32 "
        "{%0,%1,%2,%3}, {%4,%5,%6,%7}, {%8,%9}, {%0,%1,%2,%3};\n"
        : "+f"(c[0]),"+f"(c[1]),"+f"(c[2]),"+f"(c[3])
        : "r"(a[0]),"r"(a[1]),"r"(a[2]),"r"(a[3]), "r"(b[0]),"r"(b[1]));
}
__device__ __forceinline__ void ldmx4(unsigned r[4], unsigned addr){
    asm volatile("ldmatrix.sync.aligned.m8n8.x4.shared.b16 {%0,%1,%2,%3}, [%4];\n"
        : "=r"(r[0]),"=r"(r[1]),"=r"(r[2]),"=r"(r[3]) : "r"(addr));
}
__device__ __forceinline__ void ldmx2t(unsigned r[2], unsigned addr){
    asm volatile("ldmatrix.sync.aligned.m8n8.x2.trans.shared.b16 {%0,%1}, [%2];\n"
        : "=r"(r[0]),"=r"(r[1]) : "r"(addr));
}
__device__ __forceinline__ void cpa16(void* sdst, const void* gsrc){
    asm volatile("cp.async.cg.shared.global [%0], [%1], 16;\n"
        :: "r"(smem_u32(sdst)), "l"(gsrc));
}
__device__ __forceinline__ void cp_commit(){ asm volatile("cp.async.commit_group;\n"); }
template<int N> __device__ __forceinline__ void cp_wait(){
    asm volatile("cp.async.wait_group %0;\n" :: "n"(N));
}
__device__ __forceinline__ float sigmoidf_(float x){ return 1.f/(1.f+__expf(-x)); }
__device__ __forceinline__ unsigned US(const __half* p){ return *(const unsigned*)p; }

#define ZSTRIDE 136   // halves per smem row (128 data + 8 pad)

// ---------------------------------------------------------------------------
// Prepack: fp16 fragment-order weights (m16n8k16)
// ---------------------------------------------------------------------------
__global__ void __launch_bounds__(256) prepack_kernel(
    const float* __restrict__ agw, const float* __restrict__ apw,
    const float* __restrict__ bgw, const float* __restrict__ bpw,
    const float* __restrict__ gw,  const float* __restrict__ zw)
{
    int tid = blockIdx.x*256 + threadIdx.x;
    if (tid < 5*2048) {
        int m = tid >> 11, idx = tid & 2047;
        const float* W = (m==0)?agw:(m==1)?apw:(m==2)?bgw:(m==3)?bpw:gw;
        int lane = idx & 31, ks = (idx>>5) & 7, ct = idx >> 8;
        int g = lane>>2, tig = lane&3;
        const float* r0p = W + (size_t)(ct*16+g)*CDIM + ks*16 + tig*2;
        const float* r8p = r0p + 8*CDIM;
        uint4 v;
        v.x = h2u(r0p[0], r0p[1]);
        v.y = h2u(r8p[0], r8p[1]);
        v.z = h2u(r0p[8], r0p[9]);
        v.w = h2u(r8p[8], r8p[9]);
        g_wpA[tid] = v;
    } else if (tid < 5*2048 + 4096) {
        int idx = tid - 5*2048;
        int lane = idx & 31, ks = (idx>>5) & 7, j8 = idx >> 8;
        int g = lane>>2, tig = lane&3;
        const float* bp = zw + (size_t)(j8*8+g)*CDIM + ks*16 + tig*2;
        g_wpB[idx] = make_uint2(h2u(bp[0], bp[1]), h2u(bp[8], bp[9]));
    }
}

// ---------------------------------------------------------------------------
// Stage 1 (flipped GEMM, fp16): out[o][r] = W[o][:] . zn[r][:]
// 64 rows/block; warp w covers channels w*16..+15; gate split across 2 passes.
// ---------------------------------------------------------------------------
__global__ void __launch_bounds__(256,2) stage1_kernel(
    const float* __restrict__ z,   const float* __restrict__ mask,
    const float* __restrict__ lnw, const float* __restrict__ lnb,
    const float* __restrict__ agb, const float* __restrict__ apb,
    const float* __restrict__ bgb, const float* __restrict__ bpb,
    const float* __restrict__ gb)
{
    __shared__ __half s_zn[64*ZSTRIDE];   // [r][c]
    __shared__ float  s_msk[64];

    const int tid = threadIdx.x, lane = tid & 31, wid = tid >> 5;
    const int g = lane >> 2, tig = lane & 3;
    const int r0 = blockIdx.x * 64;

    if (tid < 64) s_msk[tid] = mask[r0 + tid];

    // LN: warp handles 8 rows; write fp16 zn
    {
        float4 wv = *(const float4*)(lnw + lane*4);
        float4 bv = *(const float4*)(lnb + lane*4);
        for (int it = 0; it < 8; ++it) {
            int row = wid*8 + it;
            float4 v = *(const float4*)(z + (size_t)(r0+row)*CDIM + lane*4);
            float s = v.x+v.y+v.z+v.w;
            #pragma unroll
            for (int o=16;o;o>>=1) s += __shfl_xor_sync(0xffffffffu, s, o);
            float mu = s * (1.f/CDIM);
            float dx=v.x-mu, dy=v.y-mu, dz=v.z-mu, dw=v.w-mu;
            float vv = dx*dx+dy*dy+dz*dz+dw*dw;
            #pragma unroll
            for (int o=16;o;o>>=1) vv += __shfl_xor_sync(0xffffffffu, vv, o);
            float rs = rsqrtf(vv*(1.f/CDIM) + 1e-5f);
            __half* dp = s_zn + row*ZSTRIDE + lane*4;
            *(unsigned*)(dp)     = h2u(dx*rs*wv.x+bv.x, dy*rs*wv.y+bv.y);
            *(unsigned*)(dp + 2) = h2u(dz*rs*wv.z+bv.z, dw*rs*wv.w+bv.w);
        }
    }
    __syncthreads();

    const int m0 = wid*16;
    const uint4* wbase = g_wpA + wid*256 + lane;   // [m][ct=wid][ks][lane]
    const float  bs0 = __ldg(gb+m0+g), bs8 = __ldg(gb+m0+g+8);

    #pragma unroll
    for (int ps = 0; ps < 2; ++ps) {
        const uint4* pG = wbase + (ps ? 2*2048 : 0);
        const uint4* pP = wbase + (ps ? 3*2048 : 1*2048);
        const uint4* pS = wbase + 4*2048;
        const float* b1v = ps ? bgb : agb;
        const float* b2v = ps ? bpb : apb;
        __half* dst = ps ? g_bufB : g_bufA;
        const int glo = ps*4;

        float accG[8][4], accP[8][4], accS[4][4];
        #pragma unroll
        for (int i=0;i<8;++i){
            #pragma unroll
            for (int j=0;j<4;++j){ accG[i][j]=0.f; accP[i][j]=0.f; }
        }
        #pragma unroll
        for (int i=0;i<4;++i){
            #pragma unroll
            for (int j=0;j<4;++j) accS[i][j]=0.f;
        }

        #pragma unroll 2
        for (int ks=0; ks<8; ++ks) {
            uint4 a1 = __ldg(pG + ks*32);
            uint4 a2 = __ldg(pP + ks*32);
            uint4 a3 = __ldg(pS + ks*32);
            #pragma unroll
            for (int nt=0; nt<8; ++nt) {
                const __half* bp = s_zn + (nt*8+g)*ZSTRIDE + ks*16 + 2*tig;
                unsigned b[2] = { US(bp), US(bp + 8) };
                mma_f16(accG[nt], (const unsigned*)&a1, b);
                mma_f16(accP[nt], (const unsigned*)&a2, b);
                if (nt >= glo && nt < glo+4)
                    mma_f16(accS[nt-glo], (const unsigned*)&a3, b);
            }
        }

        // pair epilogue: fp16( mask * sigmoid(G+b1) * (P+b2) ), d-major
        const float bG0 = __ldg(b1v+m0+g), bG8 = __ldg(b1v+m0+g+8);
        const float bP0 = __ldg(b2v+m0+g), bP8 = __ldg(b2v+m0+g+8);
        #pragma unroll
        for (int nt=0; nt<8; ++nt) {
            const int rr = nt*8 + tig*2;
            const float mk0 = s_msk[rr], mk1 = s_msk[rr+1];
            unsigned o0 = h2u(mk0 * sigmoidf_(accG[nt][0]+bG0) * (accP[nt][0]+bP0),
                              mk1 * sigmoidf_(accG[nt][1]+bG0) * (accP[nt][1]+bP0));
            unsigned o1 = h2u(mk0 * sigmoidf_(accG[nt][2]+bG8) * (accP[nt][2]+bP8),
                              mk1 * sigmoidf_(accG[nt][3]+bG8) * (accP[nt][3]+bP8));
            *(unsigned*)(dst + (size_t)(m0+g)*NN   + r0 + rr) = o0;
            *(unsigned*)(dst + (size_t)(m0+g+8)*NN + r0 + rr) = o1;
        }
        // gate epilogue (fp16), rows glo*8 .. glo*8+31
        #pragma unroll
        for (int nt2=0; nt2<4; ++nt2) {
            const int rr = (glo+nt2)*8 + tig*2;
            unsigned o0 = h2u(sigmoidf_(accS[nt2][0]+bs0), sigmoidf_(accS[nt2][1]+bs0));
            unsigned o1 = h2u(sigmoidf_(accS[nt2][2]+bs8), sigmoidf_(accS[nt2][3]+bs8));
            *(unsigned*)(g_bufG + (size_t)(m0+g)*NN   + r0 + rr) = o0;
            *(unsigned*)(g_bufG + (size_t)(m0+g+8)*NN + r0 + rr) = o1;
        }
    }
}

// ---------------------------------------------------------------------------
// Stage 2: per-d fp16 GEMM x[d] = a[d] @ b[d], fp16 out. 128x128 tile,
// kt=32, cp.async 2-buf, ldmatrix(+trans).
// ---------------------------------------------------------------------------
__global__ void __launch_bounds__(256,2) stage2_kernel()
{
    __shared__ __align__(16) __half As[2][128*40];   // [i][k], pad 40
    __shared__ __align__(16) __half Bs[2][32*136];   // [k][j], pad 136

    const int d = blockIdx.z;
    const __half* gA = g_bufA + (size_t)d*NN;
    const __half* gB = g_bufB + (size_t)d*NN;
    __half* gC = g_bufX + (size_t)d*NN;
    const int i0 = blockIdx.y*128, j0 = blockIdx.x*128;
    const int tid = threadIdx.x, lane = tid&31, wid = tid>>5;
    const int wm = wid & 3, wn = wid >> 2;    // 4x2 warp grid: 32 rows x 64 cols

    float acc[2][8][4];
    #pragma unroll
    for (int a=0;a<2;++a){
        #pragma unroll
        for(int b=0;b<8;++b){
            #pragma unroll
            for(int c=0;c<4;++c) acc[a][b][c]=0.f;
        }
    }

    auto load_tile = [&](int kt, int buf){
        #pragma unroll
        for (int i=0;i<2;++i){
            int cid = tid + i*256;
            int r = cid>>2, kc = (cid&3)*8;
            cpa16(&As[buf][r*40+kc], gA + (size_t)(i0+r)*NSEQ + kt + kc);
        }
        #pragma unroll
        for (int i=0;i<2;++i){
            int cid = tid + i*256;
            int kk = cid>>4, jc = (cid&15)*8;
            cpa16(&Bs[buf][kk*136+jc], gB + (size_t)(kt+kk)*NSEQ + j0 + jc);
        }
        cp_commit();
    };

    load_tile(0, 0);
    int buf = 0;
    for (int t=0; t<16; ++t) {
        if (t < 15) { load_tile((t+1)*32, buf^1); cp_wait<1>(); }
        else        { cp_wait<0>(); }
        __syncthreads();
        #pragma unroll
        for (int ks=0; ks<2; ++ks) {
            unsigned afr[2][4];
            #pragma unroll
            for (int mt=0; mt<2; ++mt)
                ldmx4(afr[mt], smem_u32(&As[buf][(wm*32 + mt*16 + (lane&15))*40
                                                 + ks*16 + (lane>>4)*8]));
            #pragma unroll
            for (int nt=0; nt<8; ++nt) {
                unsigned b[2];
                ldmx2t(b, smem_u32(&Bs[buf][(ks*16 + (lane&15))*136 + wn*64 + nt*8]));
                mma_f16(acc[0][nt], afr[0], b);
                mma_f16(acc[1][nt], afr[1], b);
            }
        }
        __syncthreads();
        buf ^= 1;
    }

    #pragma unroll
    for (int mt=0; mt<2; ++mt){
        #pragma unroll
        for (int nt=0; nt<8; ++nt) {
            int r = i0 + wm*32 + mt*16 + (lane>>2);
            int c = j0 + wn*64 + nt*8 + (lane&3)*2;
            *(unsigned*)(gC + (size_t)r*NSEQ + c)     = h2u(acc[mt][nt][0], acc[mt][nt][1]);
            *(unsigned*)(gC + (size_t)(r+8)*NSEQ + c) = h2u(acc[mt][nt][2], acc[mt][nt][3]);
        }
    }
}

// ---------------------------------------------------------------------------
// Stage 3: gather x (fp16), LN -> fp16, final projection (packed zw),
// gate (fp16) multiply, store fp32. 64 rows/block.
// Warp w: rows m0=(w&3)*16, output cols n0=(w>>2)*64.
// ---------------------------------------------------------------------------
__global__ void __launch_bounds__(256,2) stage3_kernel(
    const float* __restrict__ lnow, const float* __restrict__ lnob,
    const float* __restrict__ zb,   float* __restrict__ out)
{
    extern __shared__ char smraw[];
    float*  s_x  = (float*)smraw;                 // [64][133]  x, then gate
    __half* s_xn = (__half*)(s_x + 64*133);       // [64][ZSTRIDE] fp16

    const int tid = threadIdx.x, lane = tid&31, wid = tid>>5;
    const int g = lane >> 2, tig = lane & 3;
    const int bi = blockIdx.x;
    const int ti = bi >> 3, j0 = (bi & 7)*64;
    const size_t rbase = (size_t)ti*NSEQ + j0;

    // gather x[d][rbase + rc] (fp16) -> s_x[r][d] (fp32)
    #pragma unroll
    for (int it=0; it<8; ++it){
        int cid = tid + it*256; int dd = cid>>4; int rc = (cid&15)*4;
        uint2 v = *(const uint2*)(g_bufX + (size_t)dd*NN + rbase + rc);
        __half2 h0 = *(__half2*)&v.x, h1 = *(__half2*)&v.y;
        s_x[(rc+0)*133 + dd] = __low2float(h0);
        s_x[(rc+1)*133 + dd] = __high2float(h0);
        s_x[(rc+2)*133 + dd] = __low2float(h1);
        s_x[(rc+3)*133 + dd] = __high2float(h1);
    }
    __syncthreads();

    // LN over d -> fp16
    {
        float4 wv = *(const float4*)(lnow + lane*4);
        float4 bv = *(const float4*)(lnob + lane*4);
        for (int it=0; it<8; ++it){
            int row = wid*8 + it;
            const float* rp = s_x + row*133 + lane*4;
            float e0=rp[0], e1=rp[1], e2=rp[2], e3=rp[3];
            float s = e0+e1+e2+e3;
            #pragma unroll
            for (int o=16;o;o>>=1) s += __shfl_xor_sync(0xffffffffu, s, o);
            float mu = s*(1.f/CDIM);
            float dx=e0-mu, dy=e1-mu, dz=e2-mu, dw=e3-mu;
            float vv = dx*dx+dy*dy+dz*dz+dw*dw;
            #pragma unroll
            for (int o=16;o;o>>=1) vv += __shfl_xor_sync(0xffffffffu, vv, o);
            float rs = rsqrtf(vv*(1.f/CDIM)+1e-5f);
            __half* dp = s_xn + row*ZSTRIDE + lane*4;
            *(unsigned*)(dp)     = h2u(dx*rs*wv.x+bv.x, dy*rs*wv.y+bv.y);
            *(unsigned*)(dp + 2) = h2u(dz*rs*wv.z+bv.z, dw*rs*wv.w+bv.w);
        }
    }
    __syncthreads();

    // gate gather (fp16) overwrites s_x
    #pragma unroll
    for (int it=0; it<8; ++it){
        int cid = tid + it*256; int dd = cid>>4; int rc = (cid&15)*4;
        uint2 v = *(const uint2*)(g_bufG + (size_t)dd*NN + rbase + rc);
        __half2 h0 = *(__half2*)&v.x, h1 = *(__half2*)&v.y;
        s_x[(rc+0)*133 + dd] = __low2float(h0);
        s_x[(rc+1)*133 + dd] = __high2float(h0);
        s_x[(rc+2)*133 + dd] = __low2float(h1);
        s_x[(rc+3)*133 + dd] = __high2float(h1);
    }
    __syncthreads();

    const int m0 = (wid&3)*16, n0 = (wid>>2)*64;
    float acc[8][4];
    #pragma unroll
    for (int i=0;i<8;++i){
        #pragma unroll
        for(int j=0;j<4;++j) acc[i][j]=0.f;
    }
    #pragma unroll 2
    for (int ks=0; ks<8; ++ks) {
        unsigned a[4];
        const __half* p0 = s_xn + (m0+g)*ZSTRIDE   + ks*16 + 2*tig;
        const __half* p1 = s_xn + (m0+g+8)*ZSTRIDE + ks*16 + 2*tig;
        a[0]=US(p0); a[1]=US(p1); a[2]=US(p0+8); a[3]=US(p1+8);
        #pragma unroll
        for (int nt=0; nt<8; ++nt) {
            uint2 bw = __ldg(g_wpB + ((n0>>3)+nt)*256 + ks*32 + lane);
            unsigned b[2] = { bw.x, bw.y };
            mma_f16(acc[nt], a, b);
        }
    }

    #pragma unroll
    for (int nt=0; nt<8; ++nt){
        const int o = n0 + nt*8 + tig*2;
        const float zb0 = __ldg(zb+o), zb1 = __ldg(zb+o+1);
        {
            int r = m0 + g;
            float2 ov = make_float2((acc[nt][0]+zb0) * s_x[r*133+o],
                                    (acc[nt][1]+zb1) * s_x[r*133+o+1]);
            *(float2*)(out + (rbase + r)*CDIM + o) = ov;
        }
        {
            int r = m0 + g + 8;
            float2 ov = make_float2((acc[nt][2]+zb0) * s_x[r*133+o],
                                    (acc[nt][3]+zb1) * s_x[r*133+o+1]);
            *(float2*)(out + (rbase + r)*CDIM + o) = ov;
        }
    }
}

// ---------------------------------------------------------------------------
extern "C" void kernel_launch(void* const* d_in, const int* in_sizes, int n_in,
                              void* d_out, int out_size)
{
    const float* z    = (const float*)d_in[0];
    const float* mask = (const float*)d_in[1];
    const float* lniw = (const float*)d_in[2];
    const float* lnib = (const float*)d_in[3];
    const float* agw  = (const float*)d_in[4];
    const float* agb  = (const float*)d_in[5];
    const float* apw  = (const float*)d_in[6];
    const float* apb  = (const float*)d_in[7];
    const float* bgw  = (const float*)d_in[8];
    const float* bgb  = (const float*)d_in[9];
    const float* bpw  = (const float*)d_in[10];
    const float* bpb  = (const float*)d_in[11];
    const float* lnow = (const float*)d_in[12];
    const float* lnob = (const float*)d_in[13];
    const float* zw   = (const float*)d_in[14];
    const float* zb   = (const float*)d_in[15];
    const float* gww  = (const float*)d_in[16];
    const float* gwb  = (const float*)d_in[17];
    float* out = (float*)d_out;

    const int SMEM3 = 64*133*4 + 64*ZSTRIDE*2;     // ~51 KB
    cudaFuncSetAttribute(stage3_kernel, cudaFuncAttributeMaxDynamicSharedMemorySize, SMEM3);

    prepack_kernel<<<56, 256>>>(agw, apw, bgw, bpw, gww, zw);
    stage1_kernel<<<NN/64, 256>>>(z, mask, lniw, lnib,
                                  agb, apb, bgb, bpb, gwb);
    stage2_kernel<<<dim3(4,4,128), 256>>>();
    stage3_kernel<<<NN/64, 256, SMEM3>>>(lnow, lnob, zb, out);
}